// round 14
// baseline (speedup 1.0000x reference)
#include <cuda_runtime.h>
#include <cuda_bf16.h>
#include <math.h>
#include <stdint.h>

#define CC   128
#define TLEN 8192
#define BB   2
#define LL   20
#define TT   128
#define NTILE (BB * TLEN / TT)   // 128

// smem: 7 x 32KB rotating buffers
#define SMB(i) ((uint32_t)(i) * 32768u)
#define SMEM_TOTAL (7 * 32768)

// ---------------- device scratch ----------------
__device__ float g_h0[BB * CC * TLEN];
// weight images: [l][mat 0..4][hl 0..1][16384 bf16], swizzled [o][c] tile layout
__device__ __nv_bfloat16 g_wimg[LL * 5 * 2 * 16384];
// activation image: [ping][tile][hl][16384 bf16] — exact smem tile byte layout
__device__ __nv_bfloat16 g_img[2][NTILE][2][16384];
__device__ __nv_bfloat16 g_zero[8];   // 16B zero page (zero-initialized)

// ---------------- helpers ----------------
__device__ __forceinline__ uint32_t smem_u32(const void* p) {
    uint32_t a;
    asm("{ .reg .u64 t; cvta.to.shared.u64 t, %1; cvt.u32.u64 %0, t; }" : "=r"(a) : "l"(p));
    return a;
}
__device__ __forceinline__ uint32_t cvt_bf16x2(float hi, float lo) {
    uint32_t r; asm("cvt.rn.bf16x2.f32 %0, %1, %2;" : "=r"(r) : "f"(hi), "f"(lo)); return r;
}
__device__ __forceinline__ float bflo_f(uint32_t p) { return __uint_as_float(p << 16); }
__device__ __forceinline__ float bfhi_f(uint32_t p) { return __uint_as_float(p & 0xffff0000u); }

#define LDSM4(r, addr) \
    asm volatile("ldmatrix.sync.aligned.m8n8.x4.shared.b16 {%0,%1,%2,%3}, [%4];" \
        : "=r"((r)[0]), "=r"((r)[1]), "=r"((r)[2]), "=r"((r)[3]) : "r"(addr))
#define LDSM4T(r, addr) \
    asm volatile("ldmatrix.sync.aligned.m8n8.x4.trans.shared.b16 {%0,%1,%2,%3}, [%4];" \
        : "=r"((r)[0]), "=r"((r)[1]), "=r"((r)[2]), "=r"((r)[3]) : "r"(addr))
#define STSM4T(addr, r) \
    asm volatile("stmatrix.sync.aligned.m8n8.x4.trans.shared.b16 [%0], {%1,%2,%3,%4};" \
        :: "r"(addr), "r"((r)[0]), "r"((r)[1]), "r"((r)[2]), "r"((r)[3]))
#define MMA_BF16(d, a, b0, b1) \
    asm volatile("mma.sync.aligned.m16n8k16.row.col.f32.bf16.bf16.f32 " \
        "{%0,%1,%2,%3}, {%4,%5,%6,%7}, {%8,%9}, {%0,%1,%2,%3};" \
        : "+f"((d)[0]), "+f"((d)[1]), "+f"((d)[2]), "+f"((d)[3]) \
        : "r"((a)[0]), "r"((a)[1]), "r"((a)[2]), "r"((a)[3]), "r"(b0), "r"(b1))
#define CP_ASYNC16(saddr, gaddr) \
    asm volatile("cp.async.cg.shared.global [%0], [%1], 16;" :: "r"(saddr), "l"(gaddr))
#define CP_COMMIT() asm volatile("cp.async.commit_group;" ::: "memory")
#define CP_WAIT(n)  asm volatile("cp.async.wait_group %0;" :: "n"(n) : "memory")

// fused tanh(f) * sigmoid(g): 3 MUFU ops
__device__ __forceinline__ float gated(float f, float g) {
    float a  = fabsf(f);
    float ef = __expf(-2.0f * a);
    float eg = __expf(-g);
    float num = copysignf(1.0f - ef, f);
    return __fdividef(num, (1.0f + ef) * (1.0f + eg));
}

// ---------------- prep kernels ----------------
__global__ void prep_weights(const float* __restrict__ w_dil,
                             const float* __restrict__ w_tanh,
                             const float* __restrict__ w_sig,
                             const float* __restrict__ w_skip)
{
    int idx = blockIdx.x * blockDim.x + threadIdx.x;
    if (idx >= LL * 5 * CC * CC) return;
    int k = idx & 127;
    int o = (idx >> 7) & 127;
    int m = (idx >> 14) % 5;
    int l = idx / (5 * CC * CC);
    size_t oc = ((size_t)l * CC + o) * CC + k;
    float v;
    if (m == 0)      v = w_dil[oc * 2 + 0];
    else if (m == 1) v = w_dil[oc * 2 + 1];
    else if (m == 2) v = w_tanh[oc];
    else if (m == 3) v = w_sig[oc];
    else             v = w_skip[oc];
    __nv_bfloat16 hi = __float2bfloat16(v);
    __nv_bfloat16 lo = __float2bfloat16(v - __bfloat162float(hi));
    uint32_t byte = (uint32_t)o * 256 + ((((uint32_t)(k >> 3)) ^ (o & 7)) << 4) + (k & 7) * 2;
    size_t base = ((size_t)(l * 5 + m) * 2) * 16384;
    g_wimg[base + (byte >> 1)]         = hi;
    g_wimg[base + 16384 + (byte >> 1)] = lo;
}

__global__ void input_conv(const float* __restrict__ x,
                           const float* __restrict__ w_in,
                           const float* __restrict__ b_in)
{
    int i4 = blockIdx.x * blockDim.x + threadIdx.x;
    if (i4 >= BB * CC * TLEN / 4) return;
    int t4 = i4 & (TLEN / 4 - 1);
    int c  = (i4 >> 11) & (CC - 1);
    int b  = i4 >> 18;
    float w = w_in[c], bv = b_in[c];
    float4 xv = ((const float4*)x)[(size_t)b * (TLEN / 4) + t4];
    float4 h;
    h.x = fmaf(w, xv.x, bv); h.y = fmaf(w, xv.y, bv);
    h.z = fmaf(w, xv.z, bv); h.w = fmaf(w, xv.w, bv);
    ((float4*)g_h0)[i4] = h;
}

// build act image (ping 0) from g_h0
__global__ void __launch_bounds__(512, 1) img_build()
{
    const int blk = blockIdx.x;
    const int tid = threadIdx.x;
    const int b   = blk >> 6;
    const int t0  = (blk & 63) * TT;
    const int st_t = tid & 127;
    const int quar = tid >> 7;
    const float* src = g_h0 + (size_t)b * CC * TLEN + t0 + st_t;
    const uint32_t rowbase = (uint32_t)st_t * 256;
    const uint32_t rmask   = (uint32_t)(st_t & 7);
    char* ih = (char*)&g_img[0][blk][0][0];
    char* il = (char*)&g_img[0][blk][1][0];
#pragma unroll
    for (int jb = 0; jb < 4; ++jb) {
        int cc0 = quar * 32 + jb * 8;
        uint32_t hreg[4], lreg[4];
#pragma unroll
        for (int e = 0; e < 4; ++e) {
            float v0 = __ldg(src + (size_t)(cc0 + 2 * e) * TLEN);
            float v1 = __ldg(src + (size_t)(cc0 + 2 * e + 1) * TLEN);
            uint32_t h2 = cvt_bf16x2(v1, v0);
            hreg[e] = h2;
            lreg[e] = cvt_bf16x2(v1 - bfhi_f(h2), v0 - bflo_f(h2));
        }
        uint32_t off = rowbase + ((((uint32_t)(cc0 >> 3)) ^ rmask) << 4);
        *(uint4*)(ih + off) = make_uint4(hreg[0], hreg[1], hreg[2], hreg[3]);
        *(uint4*)(il + off) = make_uint4(lreg[0], lreg[1], lreg[2], lreg[3]);
    }
}

// ---------------- fused 3-term matrix pass (single matrix) ----------------
__device__ __forceinline__ void mma_mat3(float (&acc)[2][4][4],
                                         uint32_t wHi, uint32_t wLo,
                                         uint32_t xH, uint32_t xL,
                                         uint32_t aoff, uint32_t boff,
                                         uint32_t lmask, uint32_t asel, uint32_t bsel)
{
#pragma unroll
    for (int ks = 0; ks < 8; ++ks) {
        uint32_t acu = (((uint32_t)(2 * ks) + asel) << 4) ^ lmask;
        uint32_t ah0[4], ah1[4], al0[4], al1[4];
        LDSM4(ah0, wHi + aoff + acu);
        LDSM4(ah1, wHi + aoff + 4096 + acu);
        LDSM4(al0, wLo + aoff + acu);
        LDSM4(al1, wLo + aoff + 4096 + acu);
        uint32_t bcu = (((uint32_t)(2 * ks) + bsel) << 4) ^ lmask;
#pragma unroll
        for (int ntp = 0; ntp < 2; ++ntp) {
            uint32_t bh[4], bl[4];
            LDSM4(bh, xH + boff + (uint32_t)ntp * 4096 + bcu);
            LDSM4(bl, xL + boff + (uint32_t)ntp * 4096 + bcu);
            MMA_BF16(acc[0][2 * ntp],     ah0, bh[0], bh[1]);
            MMA_BF16(acc[0][2 * ntp + 1], ah0, bh[2], bh[3]);
            MMA_BF16(acc[1][2 * ntp],     ah1, bh[0], bh[1]);
            MMA_BF16(acc[1][2 * ntp + 1], ah1, bh[2], bh[3]);
            MMA_BF16(acc[0][2 * ntp],     ah0, bl[0], bl[1]);
            MMA_BF16(acc[0][2 * ntp + 1], ah0, bl[2], bl[3]);
            MMA_BF16(acc[1][2 * ntp],     ah1, bl[0], bl[1]);
            MMA_BF16(acc[1][2 * ntp + 1], ah1, bl[2], bl[3]);
            MMA_BF16(acc[0][2 * ntp],     al0, bh[0], bh[1]);
            MMA_BF16(acc[0][2 * ntp + 1], al0, bh[2], bh[3]);
            MMA_BF16(acc[1][2 * ntp],     al1, bh[0], bh[1]);
            MMA_BF16(acc[1][2 * ntp + 1], al1, bh[2], bh[3]);
        }
    }
}

// ---------------- fused DUAL-matrix pass: filt + gate share B operand ----------------
__device__ __forceinline__ void mma_mat23(float (&accF)[2][4][4], float (&accG)[2][4][4],
                                          uint32_t WtH, uint32_t WtL,
                                          uint32_t WsH, uint32_t WsL,
                                          uint32_t xH, uint32_t xL,
                                          uint32_t aoff, uint32_t boff,
                                          uint32_t lmask, uint32_t asel, uint32_t bsel)
{
#pragma unroll
    for (int ks = 0; ks < 8; ++ks) {
        uint32_t acu = (((uint32_t)(2 * ks) + asel) << 4) ^ lmask;
        uint32_t bcu = (((uint32_t)(2 * ks) + bsel) << 4) ^ lmask;
        uint32_t b0h[4], b0l[4], b1h[4], b1l[4];
        LDSM4(b0h, xH + boff + bcu);
        LDSM4(b0l, xL + boff + bcu);
        LDSM4(b1h, xH + boff + 4096 + bcu);
        LDSM4(b1l, xL + boff + 4096 + bcu);
        // ---- filt matrix
        {
            uint32_t a0[4], a1[4], c0[4], c1[4];
            LDSM4(a0, WtH + aoff + acu);
            LDSM4(a1, WtH + aoff + 4096 + acu);
            LDSM4(c0, WtL + aoff + acu);
            LDSM4(c1, WtL + aoff + 4096 + acu);
            MMA_BF16(accF[0][0], a0, b0h[0], b0h[1]);
            MMA_BF16(accF[0][1], a0, b0h[2], b0h[3]);
            MMA_BF16(accF[1][0], a1, b0h[0], b0h[1]);
            MMA_BF16(accF[1][1], a1, b0h[2], b0h[3]);
            MMA_BF16(accF[0][2], a0, b1h[0], b1h[1]);
            MMA_BF16(accF[0][3], a0, b1h[2], b1h[3]);
            MMA_BF16(accF[1][2], a1, b1h[0], b1h[1]);
            MMA_BF16(accF[1][3], a1, b1h[2], b1h[3]);
            MMA_BF16(accF[0][0], a0, b0l[0], b0l[1]);
            MMA_BF16(accF[0][1], a0, b0l[2], b0l[3]);
            MMA_BF16(accF[1][0], a1, b0l[0], b0l[1]);
            MMA_BF16(accF[1][1], a1, b0l[2], b0l[3]);
            MMA_BF16(accF[0][2], a0, b1l[0], b1l[1]);
            MMA_BF16(accF[0][3], a0, b1l[2], b1l[3]);
            MMA_BF16(accF[1][2], a1, b1l[0], b1l[1]);
            MMA_BF16(accF[1][3], a1, b1l[2], b1l[3]);
            MMA_BF16(accF[0][0], c0, b0h[0], b0h[1]);
            MMA_BF16(accF[0][1], c0, b0h[2], b0h[3]);
            MMA_BF16(accF[1][0], c1, b0h[0], b0h[1]);
            MMA_BF16(accF[1][1], c1, b0h[2], b0h[3]);
            MMA_BF16(accF[0][2], c0, b1h[0], b1h[1]);
            MMA_BF16(accF[0][3], c0, b1h[2], b1h[3]);
            MMA_BF16(accF[1][2], c1, b1h[0], b1h[1]);
            MMA_BF16(accF[1][3], c1, b1h[2], b1h[3]);
        }
        // ---- gate matrix (fragments reloaded, same B)
        {
            uint32_t a0[4], a1[4], c0[4], c1[4];
            LDSM4(a0, WsH + aoff + acu);
            LDSM4(a1, WsH + aoff + 4096 + acu);
            LDSM4(c0, WsL + aoff + acu);
            LDSM4(c1, WsL + aoff + 4096 + acu);
            MMA_BF16(accG[0][0], a0, b0h[0], b0h[1]);
            MMA_BF16(accG[0][1], a0, b0h[2], b0h[3]);
            MMA_BF16(accG[1][0], a1, b0h[0], b0h[1]);
            MMA_BF16(accG[1][1], a1, b0h[2], b0h[3]);
            MMA_BF16(accG[0][2], a0, b1h[0], b1h[1]);
            MMA_BF16(accG[0][3], a0, b1h[2], b1h[3]);
            MMA_BF16(accG[1][2], a1, b1h[0], b1h[1]);
            MMA_BF16(accG[1][3], a1, b1h[2], b1h[3]);
            MMA_BF16(accG[0][0], a0, b0l[0], b0l[1]);
            MMA_BF16(accG[0][1], a0, b0l[2], b0l[3]);
            MMA_BF16(accG[1][0], a1, b0l[0], b0l[1]);
            MMA_BF16(accG[1][1], a1, b0l[2], b0l[3]);
            MMA_BF16(accG[0][2], a0, b1l[0], b1l[1]);
            MMA_BF16(accG[0][3], a0, b1l[2], b1l[3]);
            MMA_BF16(accG[1][2], a1, b1l[0], b1l[1]);
            MMA_BF16(accG[1][3], a1, b1l[2], b1l[3]);
            MMA_BF16(accG[0][0], c0, b0h[0], b0h[1]);
            MMA_BF16(accG[0][1], c0, b0h[2], b0h[3]);
            MMA_BF16(accG[1][0], c1, b0h[0], b0h[1]);
            MMA_BF16(accG[1][1], c1, b0h[2], b0h[3]);
            MMA_BF16(accG[0][2], c0, b1h[0], b1h[1]);
            MMA_BF16(accG[0][3], c0, b1h[2], b1h[3]);
            MMA_BF16(accG[1][2], c1, b1h[0], b1h[1]);
            MMA_BF16(accG[1][3], c1, b1h[2], b1h[3]);
        }
    }
}

// ---------------- fused layer kernel ----------------
__global__ void __launch_bounds__(512, 1)
layer_kernel(int layer, int dil, int ping,
             const float* __restrict__ b_dil, const float* __restrict__ b_tanh,
             const float* __restrict__ b_sig, const float* __restrict__ b_skip,
             float* __restrict__ out_base)
{
    extern __shared__ char smem[];
    const uint32_t sb = smem_u32(smem);
    const int tid = threadIdx.x;
    const int wid = tid >> 5, lane = tid & 31;
    const int wm = wid & 3, wn = wid >> 2;

    const int blk = blockIdx.x;
    const int b   = blk >> 6;
    const int t0  = (blk & 63) * TT;
    float* outputs = out_base + ((size_t)layer * BB + b) * CC * TLEN;
    float* skips   = out_base + (size_t)LL * BB * CC * TLEN + ((size_t)layer * BB + b) * CC * TLEN;

    const uint32_t B0 = sb + SMB(0), B1 = sb + SMB(1), B2 = sb + SMB(2),
                   B3 = sb + SMB(3), B4 = sb + SMB(4), B5 = sb + SMB(5),
                   B6 = sb + SMB(6);

    auto prefetch_mat = [&](int m, uint32_t dh, uint32_t dl) {
        const char* gh = (const char*)(g_wimg + ((size_t)(layer * 5 + m) * 2 + 0) * 16384);
        const char* gl = (const char*)(g_wimg + ((size_t)(layer * 5 + m) * 2 + 1) * 16384);
#pragma unroll
        for (int j = 0; j < 4; ++j)
            CP_ASYNC16(dh + tid * 16 + j * 8192, gh + tid * 16 + j * 8192);
#pragma unroll
        for (int j = 0; j < 4; ++j)
            CP_ASYNC16(dl + tid * 16 + j * 8192, gl + tid * 16 + j * 8192);
        CP_COMMIT();
    };

    // hdel plane copy: swizzle-remapped cp.async from previous-layer image
    auto hdel_cp = [&](int pl, uint32_t dstbase) {
#pragma unroll
        for (int j = 0; j < 4; ++j) {
            int u = tid * 4 + j;
            int row = u >> 4, cu = u & 15;
            int sg = t0 + row - dil;
            const char* src;
            if (sg >= 0) {
                int stile = b * 64 + (sg >> 7);
                int srow  = sg & 127;
                int scu   = cu ^ ((row ^ srow) & 7);
                src = (const char*)&g_img[ping][stile][pl][0] + srow * 256 + scu * 16;
            } else {
                src = (const char*)g_zero;
            }
            CP_ASYNC16(dstbase + (uint32_t)u * 16, src);
        }
    };

    const int st_t = tid & 127;
    const int quar = tid >> 7;
    const uint32_t rowbase = (uint32_t)st_t * 256;
    const uint32_t rmask   = (uint32_t)(st_t & 7);

    const uint32_t lmask = (uint32_t)(lane & 7) << 4;
    const uint32_t asel = (uint32_t)((lane >> 4) & 1);
    const uint32_t bsel = (uint32_t)((lane >> 3) & 1);
    const uint32_t aoff = (uint32_t)(wm * 32 + (lane & 7) + ((lane >> 3) & 1) * 8) * 256;
    const uint32_t boff = (uint32_t)(wn * 32 + (lane & 7) + ((lane >> 4) & 1) * 8) * 256;
    uint32_t sunit[2];
#pragma unroll
    for (int mt = 0; mt < 2; ++mt)
        sunit[mt] = (((uint32_t)(wm * 4 + mt * 2 + ((lane >> 3) & 1))) << 4) ^ lmask;

    float accF[2][4][4];
    float accG[2][4][4];

    auto init_acc = [&](float (&A)[2][4][4], const float* bias) {
#pragma unroll
        for (int mt = 0; mt < 2; ++mt) {
            float v0 = __ldg(bias + wm * 32 + mt * 16 + (lane >> 2));
            float v1 = __ldg(bias + wm * 32 + mt * 16 + 8 + (lane >> 2));
#pragma unroll
            for (int nt = 0; nt < 4; ++nt) {
                A[mt][nt][0] = v0; A[mt][nt][1] = v0;
                A[mt][nt][2] = v1; A[mt][nt][3] = v1;
            }
        }
    };

    // ======== C0: hcur image -> B4,B5 ; hdel-hi -> B6 ========
    {
        const char* gih = (const char*)&g_img[ping][blk][0][0];
        const char* gil = (const char*)&g_img[ping][blk][1][0];
#pragma unroll
        for (int j = 0; j < 4; ++j)
            CP_ASYNC16(B4 + tid * 16 + j * 8192, gih + tid * 16 + j * 8192);
#pragma unroll
        for (int j = 0; j < 4; ++j)
            CP_ASYNC16(B5 + tid * 16 + j * 8192, gil + tid * 16 + j * 8192);
        hdel_cp(0, B6);
        CP_COMMIT();
    }
    prefetch_mat(1, B0, B1);   // C1: w_dil tap-1
    prefetch_mat(0, B2, B3);   // C2: w_dil tap-0

    init_acc(accF, b_dil + layer * CC);

    // ======== G1a: accF += W1 (x) hcur ========
    CP_WAIT(1);                // C0 + C1 done (C2 may fly)
    __syncthreads();
    mma_mat3(accF, B0, B1, B4, B5, aoff, boff, lmask, asel, bsel);

    // ---- outputs copy: reconstruct fp32 h from hcur tiles
    {
        float* outp = outputs + t0 + st_t;
#pragma unroll
        for (int jb = 0; jb < 4; ++jb) {
            int cc0 = quar * 32 + jb * 8;
            uint32_t off = rowbase + ((((uint32_t)(cc0 >> 3)) ^ rmask) << 4);
            uint4 hv = *(const uint4*)(smem + SMB(4) + off);
            uint4 lv = *(const uint4*)(smem + SMB(5) + off);
            uint32_t he[4] = {hv.x, hv.y, hv.z, hv.w};
            uint32_t le[4] = {lv.x, lv.y, lv.z, lv.w};
#pragma unroll
            for (int e = 0; e < 4; ++e) {
                outp[(size_t)(cc0 + 2 * e) * TLEN]     = bflo_f(he[e]) + bflo_f(le[e]);
                outp[(size_t)(cc0 + 2 * e + 1) * TLEN] = bfhi_f(he[e]) + bfhi_f(le[e]);
            }
        }
    }
    __syncthreads();           // B0,B1,B4,B5 free

    // ======== G1b: accF += W0 (x) hdel ========
    hdel_cp(1, B4); CP_COMMIT();   // C3: hdel-lo -> B4
    prefetch_mat(2, B0, B1);       // C4: w_tanh
    CP_WAIT(1);                    // C2 + C3 done (C4 may fly)
    __syncthreads();
    mma_mat3(accF, B2, B3, B6, B4, aoff, boff, lmask, asel, bsel);
    __syncthreads();           // B2,B3,B4,B6 free

    // ======== epi1: xdil -> (B4,B5) ========
    prefetch_mat(3, B2, B3);       // C5: w_sig
#pragma unroll
    for (int mt = 0; mt < 2; ++mt)
#pragma unroll
        for (int ntp = 0; ntp < 2; ++ntp) {
            uint32_t rh[4], rl[4];
#pragma unroll
            for (int q = 0; q < 4; ++q) {
                float d0 = accF[mt][2 * ntp + (q >> 1)][(q & 1) * 2 + 0];
                float d1 = accF[mt][2 * ntp + (q >> 1)][(q & 1) * 2 + 1];
                uint32_t h = cvt_bf16x2(d1, d0);
                rh[q] = h;
                rl[q] = cvt_bf16x2(d1 - bfhi_f(h), d0 - bflo_f(h));
            }
            uint32_t ad = boff + (uint32_t)ntp * 4096 + sunit[mt];
            STSM4T(B4 + ad, rh);
            STSM4T(B5 + ad, rl);
        }
    init_acc(accF, b_tanh + layer * CC);
    init_acc(accG, b_sig + layer * CC);
    CP_WAIT(0);                // C4 (w_tanh) + C5 (w_sig) done
    __syncthreads();           // xdil visible

    // ======== G23 fused: filt + gate over shared xdil ========
    mma_mat23(accF, accG, B0, B1, B2, B3, B4, B5, aoff, boff, lmask, asel, bsel);
    __syncthreads();           // B0,B1,B2,B3 free (B4,B5 xdil still needed)

    // ======== epi23: gated; h_next image -> (B6, B5-rewrite); xh -> (B2,B3) ========
    prefetch_mat(4, B0, B1);       // C6: w_skip
#pragma unroll
    for (int mt = 0; mt < 2; ++mt)
#pragma unroll
        for (int ntp = 0; ntp < 2; ++ntp) {
            uint32_t ad = boff + (uint32_t)ntp * 4096 + sunit[mt];
            uint32_t xdh[4], xdl[4];
            LDSM4T(xdh, B4 + ad);
            LDSM4T(xdl, B5 + ad);
            uint32_t hnh[4], hnl[4], sh[4], sl[4];
#pragma unroll
            for (int q = 0; q < 4; ++q) {
                int nt = 2 * ntp + (q >> 1), hh = q & 1;
                float xd0 = bflo_f(xdh[q]) + bflo_f(xdl[q]);
                float xd1 = bfhi_f(xdh[q]) + bfhi_f(xdl[q]);
                float xh0 = gated(accF[mt][nt][hh * 2 + 0], accG[mt][nt][hh * 2 + 0]);
                float xh1 = gated(accF[mt][nt][hh * 2 + 1], accG[mt][nt][hh * 2 + 1]);
                float hn0 = xh0 + xd0, hn1 = xh1 + xd1;
                uint32_t h2 = cvt_bf16x2(hn1, hn0);
                hnh[q] = h2;
                hnl[q] = cvt_bf16x2(hn1 - bfhi_f(h2), hn0 - bflo_f(h2));
                uint32_t x2 = cvt_bf16x2(xh1, xh0);
                sh[q] = x2;
                sl[q] = cvt_bf16x2(xh1 - bfhi_f(x2), xh0 - bflo_f(x2));
            }
            STSM4T(B6 + ad, hnh);   // h_next hi
            STSM4T(B5 + ad, hnl);   // h_next lo (rewrites xdil-lo after read)
            STSM4T(B2 + ad, sh);    // xh hi
            STSM4T(B3 + ad, sl);    // xh lo
        }
    init_acc(accF, b_skip + layer * CC);
    CP_WAIT(0);                // C6 (w_skip) done
    __syncthreads();           // xh + h_next visible, Wk loaded

    // ======== h_next image -> global ========
    {
        char* oih = (char*)&g_img[1 - ping][blk][0][0];
        char* oil = (char*)&g_img[1 - ping][blk][1][0];
#pragma unroll
        for (int j = 0; j < 4; ++j)
            *(uint4*)(oih + tid * 16 + j * 8192) = *(const uint4*)(smem + SMB(6) + tid * 16 + j * 8192);
#pragma unroll
        for (int j = 0; j < 4; ++j)
            *(uint4*)(oil + tid * 16 + j * 8192) = *(const uint4*)(smem + SMB(5) + tid * 16 + j * 8192);
    }

    // ======== G4: skip = Wk (x) xh ========
    mma_mat3(accF, B0, B1, B2, B3, aoff, boff, lmask, asel, bsel);
#pragma unroll
    for (int mt = 0; mt < 2; ++mt)
#pragma unroll
        for (int nt = 0; nt < 4; ++nt)
#pragma unroll
            for (int hh = 0; hh < 2; ++hh) {
                int o  = wm * 32 + mt * 16 + hh * 8 + (lane >> 2);
                int tg = t0 + wn * 32 + nt * 8 + (lane & 3) * 2;
                *(float2*)(skips + (size_t)o * TLEN + tg) =
                    make_float2(accF[mt][nt][hh * 2 + 0], accF[mt][nt][hh * 2 + 1]);
            }
}

// ---------------- host ----------------
extern "C" void kernel_launch(void* const* d_in, const int* in_sizes, int n_in,
                              void* d_out, int out_size)
{
    const float* x      = (const float*)d_in[0];
    const float* w_in   = (const float*)d_in[1];
    const float* b_in   = (const float*)d_in[2];
    const float* w_dil  = (const float*)d_in[3];
    const float* b_dil  = (const float*)d_in[4];
    const float* w_tanh = (const float*)d_in[5];
    const float* b_tanh = (const float*)d_in[6];
    const float* w_sig  = (const float*)d_in[7];
    const float* b_sig  = (const float*)d_in[8];
    const float* w_skip = (const float*)d_in[9];
    const float* b_skip = (const float*)d_in[10];
    float* out = (float*)d_out;

    cudaFuncSetAttribute(layer_kernel,
                         cudaFuncAttributeMaxDynamicSharedMemorySize, SMEM_TOTAL);

    prep_weights<<<(LL * 5 * CC * CC + 255) / 256, 256>>>(w_dil, w_tanh, w_sig, w_skip);
    input_conv<<<(BB * CC * TLEN / 4 + 255) / 256, 256>>>(x, w_in, b_in);
    img_build<<<NTILE, 512>>>();

    const int dils[LL] = {1, 2, 4, 8, 16, 32, 64, 128, 256, 512,
                          1, 2, 4, 8, 16, 32, 64, 128, 256, 512};
    for (int i = 0; i < LL; ++i) {
        layer_kernel<<<(BB * TLEN) / TT, 512, SMEM_TOTAL>>>(
            i, dils[i], i & 1, b_dil, b_tanh, b_sig, b_skip, out);
    }
}

// round 15
// speedup vs baseline: 1.0066x; 1.0066x over previous
#include <cuda_runtime.h>
#include <cuda_bf16.h>
#include <math.h>
#include <stdint.h>

#define CC   128
#define TLEN 8192
#define BB   2
#define LL   20
#define TT   128
#define NTILE (BB * TLEN / TT)   // 128

// smem: 7 x 32KB rotating buffers
#define SMB(i) ((uint32_t)(i) * 32768u)
#define SMEM_TOTAL (7 * 32768)

// ---------------- device scratch ----------------
__device__ float g_h0[BB * CC * TLEN];
// weight images: [l][mat 0..4][hl 0..1][16384 bf16], swizzled [o][c] tile layout
__device__ __nv_bfloat16 g_wimg[LL * 5 * 2 * 16384];
// activation image: [ping][tile][hl][16384 bf16] — exact smem tile byte layout
__device__ __nv_bfloat16 g_img[2][NTILE][2][16384];
__device__ __nv_bfloat16 g_zero[8];   // 16B zero page (zero-initialized)

// ---------------- helpers ----------------
__device__ __forceinline__ uint32_t smem_u32(const void* p) {
    uint32_t a;
    asm("{ .reg .u64 t; cvta.to.shared.u64 t, %1; cvt.u32.u64 %0, t; }" : "=r"(a) : "l"(p));
    return a;
}
__device__ __forceinline__ uint32_t cvt_bf16x2(float hi, float lo) {
    uint32_t r; asm("cvt.rn.bf16x2.f32 %0, %1, %2;" : "=r"(r) : "f"(hi), "f"(lo)); return r;
}
__device__ __forceinline__ float bflo_f(uint32_t p) { return __uint_as_float(p << 16); }
__device__ __forceinline__ float bfhi_f(uint32_t p) { return __uint_as_float(p & 0xffff0000u); }

#define LDSM4(r, addr) \
    asm volatile("ldmatrix.sync.aligned.m8n8.x4.shared.b16 {%0,%1,%2,%3}, [%4];" \
        : "=r"((r)[0]), "=r"((r)[1]), "=r"((r)[2]), "=r"((r)[3]) : "r"(addr))
#define LDSM4T(r, addr) \
    asm volatile("ldmatrix.sync.aligned.m8n8.x4.trans.shared.b16 {%0,%1,%2,%3}, [%4];" \
        : "=r"((r)[0]), "=r"((r)[1]), "=r"((r)[2]), "=r"((r)[3]) : "r"(addr))
#define STSM4T(addr, r) \
    asm volatile("stmatrix.sync.aligned.m8n8.x4.trans.shared.b16 [%0], {%1,%2,%3,%4};" \
        :: "r"(addr), "r"((r)[0]), "r"((r)[1]), "r"((r)[2]), "r"((r)[3]))
#define MMA_BF16(d, a, b0, b1) \
    asm volatile("mma.sync.aligned.m16n8k16.row.col.f32.bf16.bf16.f32 " \
        "{%0,%1,%2,%3}, {%4,%5,%6,%7}, {%8,%9}, {%0,%1,%2,%3};" \
        : "+f"((d)[0]), "+f"((d)[1]), "+f"((d)[2]), "+f"((d)[3]) \
        : "r"((a)[0]), "r"((a)[1]), "r"((a)[2]), "r"((a)[3]), "r"(b0), "r"(b1))
#define CP_ASYNC16(saddr, gaddr) \
    asm volatile("cp.async.cg.shared.global [%0], [%1], 16;" :: "r"(saddr), "l"(gaddr))
#define CP_COMMIT() asm volatile("cp.async.commit_group;" ::: "memory")
#define CP_WAIT(n)  asm volatile("cp.async.wait_group %0;" :: "n"(n) : "memory")

// fused tanh(f) * sigmoid(g): 3 MUFU ops
__device__ __forceinline__ float gated(float f, float g) {
    float a  = fabsf(f);
    float ef = __expf(-2.0f * a);
    float eg = __expf(-g);
    float num = copysignf(1.0f - ef, f);
    return __fdividef(num, (1.0f + ef) * (1.0f + eg));
}

// ---------------- prep kernels ----------------
__global__ void prep_weights(const float* __restrict__ w_dil,
                             const float* __restrict__ w_tanh,
                             const float* __restrict__ w_sig,
                             const float* __restrict__ w_skip)
{
    int idx = blockIdx.x * blockDim.x + threadIdx.x;
    if (idx >= LL * 5 * CC * CC) return;
    int k = idx & 127;
    int o = (idx >> 7) & 127;
    int m = (idx >> 14) % 5;
    int l = idx / (5 * CC * CC);
    size_t oc = ((size_t)l * CC + o) * CC + k;
    float v;
    if (m == 0)      v = w_dil[oc * 2 + 0];
    else if (m == 1) v = w_dil[oc * 2 + 1];
    else if (m == 2) v = w_tanh[oc];
    else if (m == 3) v = w_sig[oc];
    else             v = w_skip[oc];
    __nv_bfloat16 hi = __float2bfloat16(v);
    __nv_bfloat16 lo = __float2bfloat16(v - __bfloat162float(hi));
    uint32_t byte = (uint32_t)o * 256 + ((((uint32_t)(k >> 3)) ^ (o & 7)) << 4) + (k & 7) * 2;
    size_t base = ((size_t)(l * 5 + m) * 2) * 16384;
    g_wimg[base + (byte >> 1)]         = hi;
    g_wimg[base + 16384 + (byte >> 1)] = lo;
}

__global__ void input_conv(const float* __restrict__ x,
                           const float* __restrict__ w_in,
                           const float* __restrict__ b_in)
{
    int i4 = blockIdx.x * blockDim.x + threadIdx.x;
    if (i4 >= BB * CC * TLEN / 4) return;
    int t4 = i4 & (TLEN / 4 - 1);
    int c  = (i4 >> 11) & (CC - 1);
    int b  = i4 >> 18;
    float w = w_in[c], bv = b_in[c];
    float4 xv = ((const float4*)x)[(size_t)b * (TLEN / 4) + t4];
    float4 h;
    h.x = fmaf(w, xv.x, bv); h.y = fmaf(w, xv.y, bv);
    h.z = fmaf(w, xv.z, bv); h.w = fmaf(w, xv.w, bv);
    ((float4*)g_h0)[i4] = h;
}

// build act image (ping 0) from g_h0
__global__ void __launch_bounds__(512, 1) img_build()
{
    const int blk = blockIdx.x;
    const int tid = threadIdx.x;
    const int b   = blk >> 6;
    const int t0  = (blk & 63) * TT;
    const int st_t = tid & 127;
    const int quar = tid >> 7;
    const float* src = g_h0 + (size_t)b * CC * TLEN + t0 + st_t;
    const uint32_t rowbase = (uint32_t)st_t * 256;
    const uint32_t rmask   = (uint32_t)(st_t & 7);
    char* ih = (char*)&g_img[0][blk][0][0];
    char* il = (char*)&g_img[0][blk][1][0];
#pragma unroll
    for (int jb = 0; jb < 4; ++jb) {
        int cc0 = quar * 32 + jb * 8;
        uint32_t hreg[4], lreg[4];
#pragma unroll
        for (int e = 0; e < 4; ++e) {
            float v0 = __ldg(src + (size_t)(cc0 + 2 * e) * TLEN);
            float v1 = __ldg(src + (size_t)(cc0 + 2 * e + 1) * TLEN);
            uint32_t h2 = cvt_bf16x2(v1, v0);
            hreg[e] = h2;
            lreg[e] = cvt_bf16x2(v1 - bfhi_f(h2), v0 - bflo_f(h2));
        }
        uint32_t off = rowbase + ((((uint32_t)(cc0 >> 3)) ^ rmask) << 4);
        *(uint4*)(ih + off) = make_uint4(hreg[0], hreg[1], hreg[2], hreg[3]);
        *(uint4*)(il + off) = make_uint4(lreg[0], lreg[1], lreg[2], lreg[3]);
    }
}

// ---------------- fused 3-term matrix pass ----------------
__device__ __forceinline__ void mma_mat3(float (&acc)[2][4][4],
                                         uint32_t wHi, uint32_t wLo,
                                         uint32_t xH, uint32_t xL,
                                         uint32_t aoff, uint32_t boff,
                                         uint32_t lmask, uint32_t asel, uint32_t bsel)
{
#pragma unroll
    for (int ks = 0; ks < 8; ++ks) {
        uint32_t acu = (((uint32_t)(2 * ks) + asel) << 4) ^ lmask;
        uint32_t ah0[4], ah1[4], al0[4], al1[4];
        LDSM4(ah0, wHi + aoff + acu);
        LDSM4(ah1, wHi + aoff + 4096 + acu);
        LDSM4(al0, wLo + aoff + acu);
        LDSM4(al1, wLo + aoff + 4096 + acu);
        uint32_t bcu = (((uint32_t)(2 * ks) + bsel) << 4) ^ lmask;
#pragma unroll
        for (int ntp = 0; ntp < 2; ++ntp) {
            uint32_t bh[4], bl[4];
            LDSM4(bh, xH + boff + (uint32_t)ntp * 4096 + bcu);
            LDSM4(bl, xL + boff + (uint32_t)ntp * 4096 + bcu);
            MMA_BF16(acc[0][2 * ntp],     ah0, bh[0], bh[1]);
            MMA_BF16(acc[0][2 * ntp + 1], ah0, bh[2], bh[3]);
            MMA_BF16(acc[1][2 * ntp],     ah1, bh[0], bh[1]);
            MMA_BF16(acc[1][2 * ntp + 1], ah1, bh[2], bh[3]);
            MMA_BF16(acc[0][2 * ntp],     ah0, bl[0], bl[1]);
            MMA_BF16(acc[0][2 * ntp + 1], ah0, bl[2], bl[3]);
            MMA_BF16(acc[1][2 * ntp],     ah1, bl[0], bl[1]);
            MMA_BF16(acc[1][2 * ntp + 1], ah1, bl[2], bl[3]);
            MMA_BF16(acc[0][2 * ntp],     al0, bh[0], bh[1]);
            MMA_BF16(acc[0][2 * ntp + 1], al0, bh[2], bh[3]);
            MMA_BF16(acc[1][2 * ntp],     al1, bh[0], bh[1]);
            MMA_BF16(acc[1][2 * ntp + 1], al1, bh[2], bh[3]);
        }
    }
}

// ---------------- fused layer kernel ----------------
__global__ void __launch_bounds__(512, 1)
layer_kernel(int layer, int dil, int ping,
             const float* __restrict__ b_dil, const float* __restrict__ b_tanh,
             const float* __restrict__ b_sig, const float* __restrict__ b_skip,
             float* __restrict__ out_base)
{
    extern __shared__ char smem[];
    const uint32_t sb = smem_u32(smem);
    const int tid = threadIdx.x;
    const int wid = tid >> 5, lane = tid & 31;
    const int wm = wid & 3, wn = wid >> 2;

    const int blk = blockIdx.x;
    const int b   = blk >> 6;
    const int t0  = (blk & 63) * TT;
    float* outputs = out_base + ((size_t)layer * BB + b) * CC * TLEN;
    float* skips   = out_base + (size_t)LL * BB * CC * TLEN + ((size_t)layer * BB + b) * CC * TLEN;

    const uint32_t B0 = sb + SMB(0), B1 = sb + SMB(1), B2 = sb + SMB(2),
                   B3 = sb + SMB(3), B4 = sb + SMB(4), B5 = sb + SMB(5),
                   B6 = sb + SMB(6);

    // issue weight cp.asyncs WITHOUT commit (caller commits)
    auto prefetch_mat_nc = [&](int m, uint32_t dh, uint32_t dl) {
        const char* gh = (const char*)(g_wimg + ((size_t)(layer * 5 + m) * 2 + 0) * 16384);
        const char* gl = (const char*)(g_wimg + ((size_t)(layer * 5 + m) * 2 + 1) * 16384);
#pragma unroll
        for (int j = 0; j < 4; ++j)
            CP_ASYNC16(dh + tid * 16 + j * 8192, gh + tid * 16 + j * 8192);
#pragma unroll
        for (int j = 0; j < 4; ++j)
            CP_ASYNC16(dl + tid * 16 + j * 8192, gl + tid * 16 + j * 8192);
    };

    // hdel plane copy: swizzle-remapped cp.async from previous-layer image (no commit)
    auto hdel_cp = [&](int pl, uint32_t dstbase) {
#pragma unroll
        for (int j = 0; j < 4; ++j) {
            int u = tid * 4 + j;
            int row = u >> 4, cu = u & 15;
            int sg = t0 + row - dil;
            const char* src;
            if (sg >= 0) {
                int stile = b * 64 + (sg >> 7);
                int srow  = sg & 127;
                int scu   = cu ^ ((row ^ srow) & 7);
                src = (const char*)&g_img[ping][stile][pl][0] + srow * 256 + scu * 16;
            } else {
                src = (const char*)g_zero;
            }
            CP_ASYNC16(dstbase + (uint32_t)u * 16, src);
        }
    };

    const int st_t = tid & 127;
    const int quar = tid >> 7;
    const uint32_t rowbase = (uint32_t)st_t * 256;
    const uint32_t rmask   = (uint32_t)(st_t & 7);

    const uint32_t lmask = (uint32_t)(lane & 7) << 4;
    const uint32_t asel = (uint32_t)((lane >> 4) & 1);
    const uint32_t bsel = (uint32_t)((lane >> 3) & 1);
    const uint32_t aoff = (uint32_t)(wm * 32 + (lane & 7) + ((lane >> 3) & 1) * 8) * 256;
    const uint32_t boff = (uint32_t)(wn * 32 + (lane & 7) + ((lane >> 4) & 1) * 8) * 256;
    uint32_t sunit[2];
#pragma unroll
    for (int mt = 0; mt < 2; ++mt)
        sunit[mt] = (((uint32_t)(wm * 4 + mt * 2 + ((lane >> 3) & 1))) << 4) ^ lmask;

    float acc[2][4][4];
    float flt[2][4][4];

    auto init_acc = [&](const float* bias) {
#pragma unroll
        for (int mt = 0; mt < 2; ++mt) {
            float v0 = __ldg(bias + wm * 32 + mt * 16 + (lane >> 2));
            float v1 = __ldg(bias + wm * 32 + mt * 16 + 8 + (lane >> 2));
#pragma unroll
            for (int nt = 0; nt < 4; ++nt) {
                acc[mt][nt][0] = v0; acc[mt][nt][1] = v0;
                acc[mt][nt][2] = v1; acc[mt][nt][3] = v1;
            }
        }
    };

    // ======== C0: hcur image -> B4,B5 (hdel-hi deferred to C2) ========
    {
        const char* gih = (const char*)&g_img[ping][blk][0][0];
        const char* gil = (const char*)&g_img[ping][blk][1][0];
#pragma unroll
        for (int j = 0; j < 4; ++j)
            CP_ASYNC16(B4 + tid * 16 + j * 8192, gih + tid * 16 + j * 8192);
#pragma unroll
        for (int j = 0; j < 4; ++j)
            CP_ASYNC16(B5 + tid * 16 + j * 8192, gil + tid * 16 + j * 8192);
        CP_COMMIT();
    }
    prefetch_mat_nc(1, B0, B1); CP_COMMIT();   // C1: w_dil tap-1
    prefetch_mat_nc(0, B2, B3);                // C2: w_dil tap-0 ...
    hdel_cp(0, B6);                            //     ... + hdel-hi
    CP_COMMIT();

    init_acc(b_dil + layer * CC);

    // ======== G1a: acc += W1 (x) hcur ========
    CP_WAIT(1);                // C0 + C1 done (C2 may fly)
    __syncthreads();
    mma_mat3(acc, B0, B1, B4, B5, aoff, boff, lmask, asel, bsel);

    // ---- outputs copy: reconstruct fp32 h from hcur tiles
    {
        float* outp = outputs + t0 + st_t;
#pragma unroll
        for (int jb = 0; jb < 4; ++jb) {
            int cc0 = quar * 32 + jb * 8;
            uint32_t off = rowbase + ((((uint32_t)(cc0 >> 3)) ^ rmask) << 4);
            uint4 hv = *(const uint4*)(smem + SMB(4) + off);
            uint4 lv = *(const uint4*)(smem + SMB(5) + off);
            uint32_t he[4] = {hv.x, hv.y, hv.z, hv.w};
            uint32_t le[4] = {lv.x, lv.y, lv.z, lv.w};
#pragma unroll
            for (int e = 0; e < 4; ++e) {
                outp[(size_t)(cc0 + 2 * e) * TLEN]     = bflo_f(he[e]) + bflo_f(le[e]);
                outp[(size_t)(cc0 + 2 * e + 1) * TLEN] = bfhi_f(he[e]) + bfhi_f(le[e]);
            }
        }
    }
    __syncthreads();           // B0,B1,B4,B5 free

    // ======== G1b: acc += W0 (x) hdel ========
    hdel_cp(1, B4); CP_COMMIT();               // C3: hdel-lo -> B4
    prefetch_mat_nc(2, B0, B1); CP_COMMIT();   // C4: w_tanh
    CP_WAIT(1);                // C2 + C3 done (C4 may fly)
    __syncthreads();
    mma_mat3(acc, B2, B3, B6, B4, aoff, boff, lmask, asel, bsel);
    __syncthreads();           // B2,B3,B4,B6 free

    // ======== epi1: xdil -> (B2,B3) ========
    prefetch_mat_nc(3, B5, B6); CP_COMMIT();   // C5: w_sig
#pragma unroll
    for (int mt = 0; mt < 2; ++mt)
#pragma unroll
        for (int ntp = 0; ntp < 2; ++ntp) {
            uint32_t rh[4], rl[4];
#pragma unroll
            for (int q = 0; q < 4; ++q) {
                float d0 = acc[mt][2 * ntp + (q >> 1)][(q & 1) * 2 + 0];
                float d1 = acc[mt][2 * ntp + (q >> 1)][(q & 1) * 2 + 1];
                uint32_t h = cvt_bf16x2(d1, d0);
                rh[q] = h;
                rl[q] = cvt_bf16x2(d1 - bfhi_f(h), d0 - bflo_f(h));
            }
            uint32_t ad = boff + (uint32_t)ntp * 4096 + sunit[mt];
            STSM4T(B2 + ad, rh);
            STSM4T(B3 + ad, rl);
        }
    CP_WAIT(1);                // C4 (w_tanh) done (C5 may fly)
    __syncthreads();           // xdil visible

    // ======== G2: filt pre-activation kept in regs ========
    init_acc(b_tanh + layer * CC);
    mma_mat3(acc, B0, B1, B2, B3, aoff, boff, lmask, asel, bsel);
#pragma unroll
    for (int mt = 0; mt < 2; ++mt)
#pragma unroll
        for (int nt = 0; nt < 4; ++nt)
#pragma unroll
            for (int q = 0; q < 4; ++q)
                flt[mt][nt][q] = acc[mt][nt][q];
    __syncthreads();           // B0,B1 free

    // ======== G3: gate ========
    prefetch_mat_nc(4, B0, B1); CP_COMMIT();   // C6: w_skip
    init_acc(b_sig + layer * CC);
    CP_WAIT(1);                // C5 (w_sig) done (C6 may fly)
    __syncthreads();
    mma_mat3(acc, B5, B6, B2, B3, aoff, boff, lmask, asel, bsel);
    __syncthreads();           // B5,B6 free

    // ======== epi3: gated; h_next image -> (B5,B6); xh -> (B2,B3) ========
#pragma unroll
    for (int mt = 0; mt < 2; ++mt)
#pragma unroll
        for (int ntp = 0; ntp < 2; ++ntp) {
            uint32_t ad = boff + (uint32_t)ntp * 4096 + sunit[mt];
            uint32_t xdh[4], xdl[4];
            LDSM4T(xdh, B2 + ad);
            LDSM4T(xdl, B3 + ad);
            uint32_t hnh[4], hnl[4], sh[4], sl[4];
#pragma unroll
            for (int q = 0; q < 4; ++q) {
                int nt = 2 * ntp + (q >> 1), hh = q & 1;
                float xd0 = bflo_f(xdh[q]) + bflo_f(xdl[q]);
                float xd1 = bfhi_f(xdh[q]) + bfhi_f(xdl[q]);
                float xh0 = gated(flt[mt][nt][hh * 2 + 0], acc[mt][nt][hh * 2 + 0]);
                float xh1 = gated(flt[mt][nt][hh * 2 + 1], acc[mt][nt][hh * 2 + 1]);
                float hn0 = xh0 + xd0, hn1 = xh1 + xd1;
                uint32_t h2 = cvt_bf16x2(hn1, hn0);
                hnh[q] = h2;
                hnl[q] = cvt_bf16x2(hn1 - bfhi_f(h2), hn0 - bflo_f(h2));
                uint32_t x2 = cvt_bf16x2(xh1, xh0);
                sh[q] = x2;
                sl[q] = cvt_bf16x2(xh1 - bfhi_f(x2), xh0 - bflo_f(x2));
            }
            STSM4T(B5 + ad, hnh);
            STSM4T(B6 + ad, hnl);
            STSM4T(B2 + ad, sh);   // xh overwrites xdil (per-warp disjoint regions)
            STSM4T(B3 + ad, sl);
        }
    init_acc(b_skip + layer * CC);
    CP_WAIT(0);                // C6 (w_skip) done
    __syncthreads();           // xh + h_next visible, Wk loaded

    // ======== G4: skip = Wk (x) xh ========
    mma_mat3(acc, B0, B1, B2, B3, aoff, boff, lmask, asel, bsel);

    // ======== h_next image -> global (moved AFTER G4 MMA; B5,B6 stable) ========
    {
        char* oih = (char*)&g_img[1 - ping][blk][0][0];
        char* oil = (char*)&g_img[1 - ping][blk][1][0];
#pragma unroll
        for (int j = 0; j < 4; ++j)
            *(uint4*)(oih + tid * 16 + j * 8192) = *(const uint4*)(smem + SMB(5) + tid * 16 + j * 8192);
#pragma unroll
        for (int j = 0; j < 4; ++j)
            *(uint4*)(oil + tid * 16 + j * 8192) = *(const uint4*)(smem + SMB(6) + tid * 16 + j * 8192);
    }

#pragma unroll
    for (int mt = 0; mt < 2; ++mt)
#pragma unroll
        for (int nt = 0; nt < 4; ++nt)
#pragma unroll
            for (int hh = 0; hh < 2; ++hh) {
                int o  = wm * 32 + mt * 16 + hh * 8 + (lane >> 2);
                int tg = t0 + wn * 32 + nt * 8 + (lane & 3) * 2;
                *(float2*)(skips + (size_t)o * TLEN + tg) =
                    make_float2(acc[mt][nt][hh * 2 + 0], acc[mt][nt][hh * 2 + 1]);
            }
}

// ---------------- host ----------------
extern "C" void kernel_launch(void* const* d_in, const int* in_sizes, int n_in,
                              void* d_out, int out_size)
{
    const float* x      = (const float*)d_in[0];
    const float* w_in   = (const float*)d_in[1];
    const float* b_in   = (const float*)d_in[2];
    const float* w_dil  = (const float*)d_in[3];
    const float* b_dil  = (const float*)d_in[4];
    const float* w_tanh = (const float*)d_in[5];
    const float* b_tanh = (const float*)d_in[6];
    const float* w_sig  = (const float*)d_in[7];
    const float* b_sig  = (const float*)d_in[8];
    const float* w_skip = (const float*)d_in[9];
    const float* b_skip = (const float*)d_in[10];
    float* out = (float*)d_out;

    cudaFuncSetAttribute(layer_kernel,
                         cudaFuncAttributeMaxDynamicSharedMemorySize, SMEM_TOTAL);

    prep_weights<<<(LL * 5 * CC * CC + 255) / 256, 256>>>(w_dil, w_tanh, w_sig, w_skip);
    input_conv<<<(BB * CC * TLEN / 4 + 255) / 256, 256>>>(x, w_in, b_in);
    img_build<<<NTILE, 512>>>();

    const int dils[LL] = {1, 2, 4, 8, 16, 32, 64, 128, 256, 512,
                          1, 2, 4, 8, 16, 32, 64, 128, 256, 512};
    for (int i = 0; i < LL; ++i) {
        layer_kernel<<<(BB * TLEN) / TT, 512, SMEM_TOTAL>>>(
            i, dils[i], i & 1, b_dil, b_tanh, b_sig, b_skip, out);
    }
}

// round 16
// speedup vs baseline: 1.0260x; 1.0193x over previous
#include <cuda_runtime.h>
#include <cuda_bf16.h>
#include <math.h>
#include <stdint.h>

#define CC   128
#define TLEN 8192
#define BB   2
#define LL   20
#define TT   128
#define NTILE (BB * TLEN / TT)   // 128

// smem: 7 x 32KB rotating buffers
#define SMB(i) ((uint32_t)(i) * 32768u)
#define SMEM_TOTAL (7 * 32768)

// ---------------- device scratch ----------------
__device__ float g_h0[BB * CC * TLEN];
// weight images: [l][mat 0..4][hl 0..1][16384 bf16], swizzled [o][c] tile layout
__device__ __nv_bfloat16 g_wimg[LL * 5 * 2 * 16384];
// activation image: [ping][tile][hl][16384 bf16] — exact smem tile byte layout
__device__ __nv_bfloat16 g_img[2][NTILE][2][16384];
__device__ __nv_bfloat16 g_zero[8];   // 16B zero page (zero-initialized)

// ---------------- helpers ----------------
__device__ __forceinline__ uint32_t smem_u32(const void* p) {
    uint32_t a;
    asm("{ .reg .u64 t; cvta.to.shared.u64 t, %1; cvt.u32.u64 %0, t; }" : "=r"(a) : "l"(p));
    return a;
}
__device__ __forceinline__ uint32_t cvt_bf16x2(float hi, float lo) {
    uint32_t r; asm("cvt.rn.bf16x2.f32 %0, %1, %2;" : "=r"(r) : "f"(hi), "f"(lo)); return r;
}
__device__ __forceinline__ float bflo_f(uint32_t p) { return __uint_as_float(p << 16); }
__device__ __forceinline__ float bfhi_f(uint32_t p) { return __uint_as_float(p & 0xffff0000u); }

#define LDSM4(r, addr) \
    asm volatile("ldmatrix.sync.aligned.m8n8.x4.shared.b16 {%0,%1,%2,%3}, [%4];" \
        : "=r"((r)[0]), "=r"((r)[1]), "=r"((r)[2]), "=r"((r)[3]) : "r"(addr))
#define LDSM4T(r, addr) \
    asm volatile("ldmatrix.sync.aligned.m8n8.x4.trans.shared.b16 {%0,%1,%2,%3}, [%4];" \
        : "=r"((r)[0]), "=r"((r)[1]), "=r"((r)[2]), "=r"((r)[3]) : "r"(addr))
#define STSM4T(addr, r) \
    asm volatile("stmatrix.sync.aligned.m8n8.x4.trans.shared.b16 [%0], {%1,%2,%3,%4};" \
        :: "r"(addr), "r"((r)[0]), "r"((r)[1]), "r"((r)[2]), "r"((r)[3]))
#define MMA_BF16(d, a, b0, b1) \
    asm volatile("mma.sync.aligned.m16n8k16.row.col.f32.bf16.bf16.f32 " \
        "{%0,%1,%2,%3}, {%4,%5,%6,%7}, {%8,%9}, {%0,%1,%2,%3};" \
        : "+f"((d)[0]), "+f"((d)[1]), "+f"((d)[2]), "+f"((d)[3]) \
        : "r"((a)[0]), "r"((a)[1]), "r"((a)[2]), "r"((a)[3]), "r"(b0), "r"(b1))
#define CP_ASYNC16(saddr, gaddr) \
    asm volatile("cp.async.cg.shared.global [%0], [%1], 16;" :: "r"(saddr), "l"(gaddr))
#define CP_COMMIT() asm volatile("cp.async.commit_group;" ::: "memory")
#define CP_WAIT(n)  asm volatile("cp.async.wait_group %0;" :: "n"(n) : "memory")

// fused tanh(f) * sigmoid(g): 3 MUFU ops
__device__ __forceinline__ float gated(float f, float g) {
    float a  = fabsf(f);
    float ef = __expf(-2.0f * a);
    float eg = __expf(-g);
    float num = copysignf(1.0f - ef, f);
    return __fdividef(num, (1.0f + ef) * (1.0f + eg));
}

// ---------------- prep kernels ----------------
__global__ void prep_weights(const float* __restrict__ w_dil,
                             const float* __restrict__ w_tanh,
                             const float* __restrict__ w_sig,
                             const float* __restrict__ w_skip)
{
    int idx = blockIdx.x * blockDim.x + threadIdx.x;
    if (idx >= LL * 5 * CC * CC) return;
    int k = idx & 127;
    int o = (idx >> 7) & 127;
    int m = (idx >> 14) % 5;
    int l = idx / (5 * CC * CC);
    size_t oc = ((size_t)l * CC + o) * CC + k;
    float v;
    if (m == 0)      v = w_dil[oc * 2 + 0];
    else if (m == 1) v = w_dil[oc * 2 + 1];
    else if (m == 2) v = w_tanh[oc];
    else if (m == 3) v = w_sig[oc];
    else             v = w_skip[oc];
    __nv_bfloat16 hi = __float2bfloat16(v);
    __nv_bfloat16 lo = __float2bfloat16(v - __bfloat162float(hi));
    uint32_t byte = (uint32_t)o * 256 + ((((uint32_t)(k >> 3)) ^ (o & 7)) << 4) + (k & 7) * 2;
    size_t base = ((size_t)(l * 5 + m) * 2) * 16384;
    g_wimg[base + (byte >> 1)]         = hi;
    g_wimg[base + 16384 + (byte >> 1)] = lo;
}

__global__ void input_conv(const float* __restrict__ x,
                           const float* __restrict__ w_in,
                           const float* __restrict__ b_in)
{
    int i4 = blockIdx.x * blockDim.x + threadIdx.x;
    if (i4 >= BB * CC * TLEN / 4) return;
    int t4 = i4 & (TLEN / 4 - 1);
    int c  = (i4 >> 11) & (CC - 1);
    int b  = i4 >> 18;
    float w = w_in[c], bv = b_in[c];
    float4 xv = ((const float4*)x)[(size_t)b * (TLEN / 4) + t4];
    float4 h;
    h.x = fmaf(w, xv.x, bv); h.y = fmaf(w, xv.y, bv);
    h.z = fmaf(w, xv.z, bv); h.w = fmaf(w, xv.w, bv);
    ((float4*)g_h0)[i4] = h;
}

// build act image (ping 0) from g_h0
__global__ void __launch_bounds__(512, 1) img_build()
{
    const int blk = blockIdx.x;
    const int tid = threadIdx.x;
    const int b   = blk >> 6;
    const int t0  = (blk & 63) * TT;
    const int st_t = tid & 127;
    const int quar = tid >> 7;
    const float* src = g_h0 + (size_t)b * CC * TLEN + t0 + st_t;
    const uint32_t rowbase = (uint32_t)st_t * 256;
    const uint32_t rmask   = (uint32_t)(st_t & 7);
    char* ih = (char*)&g_img[0][blk][0][0];
    char* il = (char*)&g_img[0][blk][1][0];
#pragma unroll
    for (int jb = 0; jb < 4; ++jb) {
        int cc0 = quar * 32 + jb * 8;
        uint32_t hreg[4], lreg[4];
#pragma unroll
        for (int e = 0; e < 4; ++e) {
            float v0 = __ldg(src + (size_t)(cc0 + 2 * e) * TLEN);
            float v1 = __ldg(src + (size_t)(cc0 + 2 * e + 1) * TLEN);
            uint32_t h2 = cvt_bf16x2(v1, v0);
            hreg[e] = h2;
            lreg[e] = cvt_bf16x2(v1 - bfhi_f(h2), v0 - bflo_f(h2));
        }
        uint32_t off = rowbase + ((((uint32_t)(cc0 >> 3)) ^ rmask) << 4);
        *(uint4*)(ih + off) = make_uint4(hreg[0], hreg[1], hreg[2], hreg[3]);
        *(uint4*)(il + off) = make_uint4(lreg[0], lreg[1], lreg[2], lreg[3]);
    }
}

// ---------------- fused 3-term matrix pass ----------------
__device__ __forceinline__ void mma_mat3(float (&acc)[2][4][4],
                                         uint32_t wHi, uint32_t wLo,
                                         uint32_t xH, uint32_t xL,
                                         uint32_t aoff, uint32_t boff,
                                         uint32_t lmask, uint32_t asel, uint32_t bsel)
{
#pragma unroll
    for (int ks = 0; ks < 8; ++ks) {
        uint32_t acu = (((uint32_t)(2 * ks) + asel) << 4) ^ lmask;
        uint32_t ah0[4], ah1[4], al0[4], al1[4];
        LDSM4(ah0, wHi + aoff + acu);
        LDSM4(ah1, wHi + aoff + 4096 + acu);
        LDSM4(al0, wLo + aoff + acu);
        LDSM4(al1, wLo + aoff + 4096 + acu);
        uint32_t bcu = (((uint32_t)(2 * ks) + bsel) << 4) ^ lmask;
#pragma unroll
        for (int ntp = 0; ntp < 2; ++ntp) {
            uint32_t bh[4], bl[4];
            LDSM4(bh, xH + boff + (uint32_t)ntp * 4096 + bcu);
            LDSM4(bl, xL + boff + (uint32_t)ntp * 4096 + bcu);
            MMA_BF16(acc[0][2 * ntp],     ah0, bh[0], bh[1]);
            MMA_BF16(acc[0][2 * ntp + 1], ah0, bh[2], bh[3]);
            MMA_BF16(acc[1][2 * ntp],     ah1, bh[0], bh[1]);
            MMA_BF16(acc[1][2 * ntp + 1], ah1, bh[2], bh[3]);
            MMA_BF16(acc[0][2 * ntp],     ah0, bl[0], bl[1]);
            MMA_BF16(acc[0][2 * ntp + 1], ah0, bl[2], bl[3]);
            MMA_BF16(acc[1][2 * ntp],     ah1, bl[0], bl[1]);
            MMA_BF16(acc[1][2 * ntp + 1], ah1, bl[2], bl[3]);
            MMA_BF16(acc[0][2 * ntp],     al0, bh[0], bh[1]);
            MMA_BF16(acc[0][2 * ntp + 1], al0, bh[2], bh[3]);
            MMA_BF16(acc[1][2 * ntp],     al1, bh[0], bh[1]);
            MMA_BF16(acc[1][2 * ntp + 1], al1, bh[2], bh[3]);
        }
    }
}

// ---------------- fused layer kernel ----------------
__global__ void __launch_bounds__(512, 1)
layer_kernel(int layer, int dil, int ping,
             const float* __restrict__ b_dil, const float* __restrict__ b_tanh,
             const float* __restrict__ b_sig, const float* __restrict__ b_skip,
             float* __restrict__ out_base)
{
    extern __shared__ char smem[];
    const uint32_t sb = smem_u32(smem);
    const int tid = threadIdx.x;
    const int wid = tid >> 5, lane = tid & 31;
    const int wm = wid & 3, wn = wid >> 2;

    const int blk = blockIdx.x;
    const int b   = blk >> 6;
    const int t0  = (blk & 63) * TT;
    float* outputs = out_base + ((size_t)layer * BB + b) * CC * TLEN;
    float* skips   = out_base + (size_t)LL * BB * CC * TLEN + ((size_t)layer * BB + b) * CC * TLEN;

    const uint32_t B0 = sb + SMB(0), B1 = sb + SMB(1), B2 = sb + SMB(2),
                   B3 = sb + SMB(3), B4 = sb + SMB(4), B5 = sb + SMB(5),
                   B6 = sb + SMB(6);

    // single weight plane cp.async (16KB -> one 32KB-slot plane, no commit)
    auto prefetch_plane = [&](int m, int hl, uint32_t dst) {
        const char* g = (const char*)(g_wimg + ((size_t)(layer * 5 + m) * 2 + hl) * 16384);
#pragma unroll
        for (int j = 0; j < 4; ++j)
            CP_ASYNC16(dst + tid * 16 + j * 8192, g + tid * 16 + j * 8192);
    };

    // hdel plane copy: swizzle-remapped cp.async from previous-layer image (no commit)
    auto hdel_cp = [&](int pl, uint32_t dstbase) {
#pragma unroll
        for (int j = 0; j < 4; ++j) {
            int u = tid * 4 + j;
            int row = u >> 4, cu = u & 15;
            int sg = t0 + row - dil;
            const char* src;
            if (sg >= 0) {
                int stile = b * 64 + (sg >> 7);
                int srow  = sg & 127;
                int scu   = cu ^ ((row ^ srow) & 7);
                src = (const char*)&g_img[ping][stile][pl][0] + srow * 256 + scu * 16;
            } else {
                src = (const char*)g_zero;
            }
            CP_ASYNC16(dstbase + (uint32_t)u * 16, src);
        }
    };

    const int st_t = tid & 127;
    const int quar = tid >> 7;
    const uint32_t rowbase = (uint32_t)st_t * 256;
    const uint32_t rmask   = (uint32_t)(st_t & 7);

    const uint32_t lmask = (uint32_t)(lane & 7) << 4;
    const uint32_t asel = (uint32_t)((lane >> 4) & 1);
    const uint32_t bsel = (uint32_t)((lane >> 3) & 1);
    const uint32_t aoff = (uint32_t)(wm * 32 + (lane & 7) + ((lane >> 3) & 1) * 8) * 256;
    const uint32_t boff = (uint32_t)(wn * 32 + (lane & 7) + ((lane >> 4) & 1) * 8) * 256;
    uint32_t sunit[2];
#pragma unroll
    for (int mt = 0; mt < 2; ++mt)
        sunit[mt] = (((uint32_t)(wm * 4 + mt * 2 + ((lane >> 3) & 1))) << 4) ^ lmask;

    float acc[2][4][4];
    float flt[2][4][4];

    auto init_acc = [&](const float* bias) {
#pragma unroll
        for (int mt = 0; mt < 2; ++mt) {
            float v0 = __ldg(bias + wm * 32 + mt * 16 + (lane >> 2));
            float v1 = __ldg(bias + wm * 32 + mt * 16 + 8 + (lane >> 2));
#pragma unroll
            for (int nt = 0; nt < 4; ++nt) {
                acc[mt][nt][0] = v0; acc[mt][nt][1] = v0;
                acc[mt][nt][2] = v1; acc[mt][nt][3] = v1;
            }
        }
    };

    // ======== C0: hcur image -> B4,B5 ; hdel-hi -> B6 ========
    {
        const char* gih = (const char*)&g_img[ping][blk][0][0];
        const char* gil = (const char*)&g_img[ping][blk][1][0];
#pragma unroll
        for (int j = 0; j < 4; ++j)
            CP_ASYNC16(B4 + tid * 16 + j * 8192, gih + tid * 16 + j * 8192);
#pragma unroll
        for (int j = 0; j < 4; ++j)
            CP_ASYNC16(B5 + tid * 16 + j * 8192, gil + tid * 16 + j * 8192);
        hdel_cp(0, B6);
        CP_COMMIT();
    }
    prefetch_plane(1, 0, B0); prefetch_plane(1, 1, B1); CP_COMMIT();   // C1: W1
    prefetch_plane(0, 0, B2); prefetch_plane(0, 1, B3); CP_COMMIT();   // C2: W0

    init_acc(b_dil + layer * CC);

    // ======== G1a: acc += W1 (x) hcur ========
    CP_WAIT(1);                // C0 + C1 done (C2 may fly)
    __syncthreads();           // S1
    mma_mat3(acc, B0, B1, B4, B5, aoff, boff, lmask, asel, bsel);

    // ---- outputs copy: reconstruct fp32 h from hcur tiles
    {
        float* outp = outputs + t0 + st_t;
#pragma unroll
        for (int jb = 0; jb < 4; ++jb) {
            int cc0 = quar * 32 + jb * 8;
            uint32_t off = rowbase + ((((uint32_t)(cc0 >> 3)) ^ rmask) << 4);
            uint4 hv = *(const uint4*)(smem + SMB(4) + off);
            uint4 lv = *(const uint4*)(smem + SMB(5) + off);
            uint32_t he[4] = {hv.x, hv.y, hv.z, hv.w};
            uint32_t le[4] = {lv.x, lv.y, lv.z, lv.w};
#pragma unroll
            for (int e = 0; e < 4; ++e) {
                outp[(size_t)(cc0 + 2 * e) * TLEN]     = bflo_f(he[e]) + bflo_f(le[e]);
                outp[(size_t)(cc0 + 2 * e + 1) * TLEN] = bfhi_f(he[e]) + bfhi_f(le[e]);
            }
        }
    }
    __syncthreads();           // S2a: B0,B1,B4,B5 free

    // ======== G1b prep: hdel-lo, Wt, Ws-hi all in flight ========
    hdel_cp(1, B4); CP_COMMIT();                                        // C3: hdel-lo -> B4
    prefetch_plane(2, 0, B0); prefetch_plane(2, 1, B1); CP_COMMIT();    // C4: Wt -> B0,B1
    prefetch_plane(3, 0, B5); CP_COMMIT();                              // C5: Ws-hi -> B5
    CP_WAIT(2);                // C2 (W0) + C3 (hdel-lo) done; C4,C5 fly
    __syncthreads();           // S2b
    mma_mat3(acc, B2, B3, B6, B4, aoff, boff, lmask, asel, bsel);
    __syncthreads();           // S3a: B2,B3,B6,B4 free

    // ======== epi1: xdil -> (B2,B3); Ws-lo + Wk-hi in flight ========
    prefetch_plane(3, 1, B6); CP_COMMIT();                              // C6: Ws-lo -> B6
    prefetch_plane(4, 0, B4); CP_COMMIT();                              // C7: Wk-hi -> B4
#pragma unroll
    for (int mt = 0; mt < 2; ++mt)
#pragma unroll
        for (int ntp = 0; ntp < 2; ++ntp) {
            uint32_t rh[4], rl[4];
#pragma unroll
            for (int q = 0; q < 4; ++q) {
                float d0 = acc[mt][2 * ntp + (q >> 1)][(q & 1) * 2 + 0];
                float d1 = acc[mt][2 * ntp + (q >> 1)][(q & 1) * 2 + 1];
                uint32_t h = cvt_bf16x2(d1, d0);
                rh[q] = h;
                rl[q] = cvt_bf16x2(d1 - bfhi_f(h), d0 - bflo_f(h));
            }
            uint32_t ad = boff + (uint32_t)ntp * 4096 + sunit[mt];
            STSM4T(B2 + ad, rh);
            STSM4T(B3 + ad, rl);
        }
    CP_WAIT(1);                // C4 (Wt) + C5 (Ws-hi) + C6 (Ws-lo) done; C7 flies
    __syncthreads();           // S3b: xdil + Wt + Ws all visible

    // ======== G2 + G3 merged: filt then gate, NO intermediate barrier ========
    init_acc(b_tanh + layer * CC);
    mma_mat3(acc, B0, B1, B2, B3, aoff, boff, lmask, asel, bsel);
#pragma unroll
    for (int mt = 0; mt < 2; ++mt)
#pragma unroll
        for (int nt = 0; nt < 4; ++nt)
#pragma unroll
            for (int q = 0; q < 4; ++q)
                flt[mt][nt][q] = acc[mt][nt][q];
    init_acc(b_sig + layer * CC);
    mma_mat3(acc, B5, B6, B2, B3, aoff, boff, lmask, asel, bsel);
    __syncthreads();           // S4a: B0,B1 (Wt) + B5,B6 (Ws) free

    // ======== epi3: gated; h_next image -> (B5,B6); xh -> (B2,B3) ========
    prefetch_plane(4, 1, B0); CP_COMMIT();                              // C8: Wk-lo -> B0
#pragma unroll
    for (int mt = 0; mt < 2; ++mt)
#pragma unroll
        for (int ntp = 0; ntp < 2; ++ntp) {
            uint32_t ad = boff + (uint32_t)ntp * 4096 + sunit[mt];
            uint32_t xdh[4], xdl[4];
            LDSM4T(xdh, B2 + ad);
            LDSM4T(xdl, B3 + ad);
            uint32_t hnh[4], hnl[4], sh[4], sl[4];
#pragma unroll
            for (int q = 0; q < 4; ++q) {
                int nt = 2 * ntp + (q >> 1), hh = q & 1;
                float xd0 = bflo_f(xdh[q]) + bflo_f(xdl[q]);
                float xd1 = bfhi_f(xdh[q]) + bfhi_f(xdl[q]);
                float xh0 = gated(flt[mt][nt][hh * 2 + 0], acc[mt][nt][hh * 2 + 0]);
                float xh1 = gated(flt[mt][nt][hh * 2 + 1], acc[mt][nt][hh * 2 + 1]);
                float hn0 = xh0 + xd0, hn1 = xh1 + xd1;
                uint32_t h2 = cvt_bf16x2(hn1, hn0);
                hnh[q] = h2;
                hnl[q] = cvt_bf16x2(hn1 - bfhi_f(h2), hn0 - bflo_f(h2));
                uint32_t x2 = cvt_bf16x2(xh1, xh0);
                sh[q] = x2;
                sl[q] = cvt_bf16x2(xh1 - bfhi_f(x2), xh0 - bflo_f(x2));
            }
            STSM4T(B5 + ad, hnh);
            STSM4T(B6 + ad, hnl);
            STSM4T(B2 + ad, sh);   // xh overwrites xdil (per-warp disjoint regions)
            STSM4T(B3 + ad, sl);
        }
    init_acc(b_skip + layer * CC);
    CP_WAIT(0);                // C7 (Wk-hi) + C8 (Wk-lo) done
    __syncthreads();           // S4b: xh + h_next visible, Wk loaded

    // ======== h_next image -> global ========
    {
        char* oih = (char*)&g_img[1 - ping][blk][0][0];
        char* oil = (char*)&g_img[1 - ping][blk][1][0];
#pragma unroll
        for (int j = 0; j < 4; ++j)
            *(uint4*)(oih + tid * 16 + j * 8192) = *(const uint4*)(smem + SMB(5) + tid * 16 + j * 8192);
#pragma unroll
        for (int j = 0; j < 4; ++j)
            *(uint4*)(oil + tid * 16 + j * 8192) = *(const uint4*)(smem + SMB(6) + tid * 16 + j * 8192);
    }

    // ======== G4: skip = Wk (x) xh  (Wk-hi in B4, Wk-lo in B0) ========
    mma_mat3(acc, B4, B0, B2, B3, aoff, boff, lmask, asel, bsel);
#pragma unroll
    for (int mt = 0; mt < 2; ++mt)
#pragma unroll
        for (int nt = 0; nt < 4; ++nt)
#pragma unroll
            for (int hh = 0; hh < 2; ++hh) {
                int o  = wm * 32 + mt * 16 + hh * 8 + (lane >> 2);
                int tg = t0 + wn * 32 + nt * 8 + (lane & 3) * 2;
                *(float2*)(skips + (size_t)o * TLEN + tg) =
                    make_float2(acc[mt][nt][hh * 2 + 0], acc[mt][nt][hh * 2 + 1]);
            }
}

// ---------------- host ----------------
extern "C" void kernel_launch(void* const* d_in, const int* in_sizes, int n_in,
                              void* d_out, int out_size)
{
    const float* x      = (const float*)d_in[0];
    const float* w_in   = (const float*)d_in[1];
    const float* b_in   = (const float*)d_in[2];
    const float* w_dil  = (const float*)d_in[3];
    const float* b_dil  = (const float*)d_in[4];
    const float* w_tanh = (const float*)d_in[5];
    const float* b_tanh = (const float*)d_in[6];
    const float* w_sig  = (const float*)d_in[7];
    const float* b_sig  = (const float*)d_in[8];
    const float* w_skip = (const float*)d_in[9];
    const float* b_skip = (const float*)d_in[10];
    float* out = (float*)d_out;

    cudaFuncSetAttribute(layer_kernel,
                         cudaFuncAttributeMaxDynamicSharedMemorySize, SMEM_TOTAL);

    prep_weights<<<(LL * 5 * CC * CC + 255) / 256, 256>>>(w_dil, w_tanh, w_sig, w_skip);
    input_conv<<<(BB * CC * TLEN / 4 + 255) / 256, 256>>>(x, w_in, b_in);
    img_build<<<NTILE, 512>>>();

    const int dils[LL] = {1, 2, 4, 8, 16, 32, 64, 128, 256, 512,
                          1, 2, 4, 8, 16, 32, 64, 128, 256, 512};
    for (int i = 0; i < LL; ++i) {
        layer_kernel<<<(BB * TLEN) / TT, 512, SMEM_TOTAL>>>(
            i, dils[i], i & 1, b_dil, b_tanh, b_sig, b_skip, out);
    }
}

// round 17
// speedup vs baseline: 1.0560x; 1.0293x over previous
#include <cuda_runtime.h>
#include <cuda_bf16.h>
#include <math.h>
#include <stdint.h>

#define CC   128
#define TLEN 8192
#define BB   2
#define LL   20
#define TT   128
#define NTILE (BB * TLEN / TT)   // 128

// smem: 7 x 32KB rotating buffers + 2KB bias area
#define SMB(i) ((uint32_t)(i) * 32768u)
#define SM_BIAS (7 * 32768)
#define SMEM_TOTAL (7 * 32768 + 2048)

// ---------------- device scratch ----------------
__device__ float g_h0[BB * CC * TLEN];
// weight images: [l][mat 0..4][hl 0..1][16384 bf16], swizzled [o][c] tile layout
__device__ __nv_bfloat16 g_wimg[LL * 5 * 2 * 16384];
// activation image: [ping][tile][hl][16384 bf16] — exact smem tile byte layout
__device__ __nv_bfloat16 g_img[2][NTILE][2][16384];
__device__ __nv_bfloat16 g_zero[8];   // 16B zero page (zero-initialized)

// ---------------- helpers ----------------
__device__ __forceinline__ uint32_t smem_u32(const void* p) {
    uint32_t a;
    asm("{ .reg .u64 t; cvta.to.shared.u64 t, %1; cvt.u32.u64 %0, t; }" : "=r"(a) : "l"(p));
    return a;
}
__device__ __forceinline__ uint32_t cvt_bf16x2(float hi, float lo) {
    uint32_t r; asm("cvt.rn.bf16x2.f32 %0, %1, %2;" : "=r"(r) : "f"(hi), "f"(lo)); return r;
}
__device__ __forceinline__ float bflo_f(uint32_t p) { return __uint_as_float(p << 16); }
__device__ __forceinline__ float bfhi_f(uint32_t p) { return __uint_as_float(p & 0xffff0000u); }

#define LDSM4(r, addr) \
    asm volatile("ldmatrix.sync.aligned.m8n8.x4.shared.b16 {%0,%1,%2,%3}, [%4];" \
        : "=r"((r)[0]), "=r"((r)[1]), "=r"((r)[2]), "=r"((r)[3]) : "r"(addr))
#define LDSM4T(r, addr) \
    asm volatile("ldmatrix.sync.aligned.m8n8.x4.trans.shared.b16 {%0,%1,%2,%3}, [%4];" \
        : "=r"((r)[0]), "=r"((r)[1]), "=r"((r)[2]), "=r"((r)[3]) : "r"(addr))
#define STSM4T(addr, r) \
    asm volatile("stmatrix.sync.aligned.m8n8.x4.trans.shared.b16 [%0], {%1,%2,%3,%4};" \
        :: "r"(addr), "r"((r)[0]), "r"((r)[1]), "r"((r)[2]), "r"((r)[3]))
#define MMA_BF16(d, a, b0, b1) \
    asm volatile("mma.sync.aligned.m16n8k16.row.col.f32.bf16.bf16.f32 " \
        "{%0,%1,%2,%3}, {%4,%5,%6,%7}, {%8,%9}, {%0,%1,%2,%3};" \
        : "+f"((d)[0]), "+f"((d)[1]), "+f"((d)[2]), "+f"((d)[3]) \
        : "r"((a)[0]), "r"((a)[1]), "r"((a)[2]), "r"((a)[3]), "r"(b0), "r"(b1))
#define CP_ASYNC16(saddr, gaddr) \
    asm volatile("cp.async.cg.shared.global [%0], [%1], 16;" :: "r"(saddr), "l"(gaddr))
#define CP_COMMIT() asm volatile("cp.async.commit_group;" ::: "memory")
#define CP_WAIT(n)  asm volatile("cp.async.wait_group %0;" :: "n"(n) : "memory")

// fused tanh(f) * sigmoid(g): 3 MUFU ops
__device__ __forceinline__ float gated(float f, float g) {
    float a  = fabsf(f);
    float ef = __expf(-2.0f * a);
    float eg = __expf(-g);
    float num = copysignf(1.0f - ef, f);
    return __fdividef(num, (1.0f + ef) * (1.0f + eg));
}

// ---------------- prep kernels ----------------
__global__ void prep_weights(const float* __restrict__ w_dil,
                             const float* __restrict__ w_tanh,
                             const float* __restrict__ w_sig,
                             const float* __restrict__ w_skip)
{
    int idx = blockIdx.x * blockDim.x + threadIdx.x;
    if (idx >= LL * 5 * CC * CC) return;
    int k = idx & 127;
    int o = (idx >> 7) & 127;
    int m = (idx >> 14) % 5;
    int l = idx / (5 * CC * CC);
    size_t oc = ((size_t)l * CC + o) * CC + k;
    float v;
    if (m == 0)      v = w_dil[oc * 2 + 0];
    else if (m == 1) v = w_dil[oc * 2 + 1];
    else if (m == 2) v = w_tanh[oc];
    else if (m == 3) v = w_sig[oc];
    else             v = w_skip[oc];
    __nv_bfloat16 hi = __float2bfloat16(v);
    __nv_bfloat16 lo = __float2bfloat16(v - __bfloat162float(hi));
    uint32_t byte = (uint32_t)o * 256 + ((((uint32_t)(k >> 3)) ^ (o & 7)) << 4) + (k & 7) * 2;
    size_t base = ((size_t)(l * 5 + m) * 2) * 16384;
    g_wimg[base + (byte >> 1)]         = hi;
    g_wimg[base + 16384 + (byte >> 1)] = lo;
}

__global__ void input_conv(const float* __restrict__ x,
                           const float* __restrict__ w_in,
                           const float* __restrict__ b_in)
{
    int i4 = blockIdx.x * blockDim.x + threadIdx.x;
    if (i4 >= BB * CC * TLEN / 4) return;
    int t4 = i4 & (TLEN / 4 - 1);
    int c  = (i4 >> 11) & (CC - 1);
    int b  = i4 >> 18;
    float w = w_in[c], bv = b_in[c];
    float4 xv = ((const float4*)x)[(size_t)b * (TLEN / 4) + t4];
    float4 h;
    h.x = fmaf(w, xv.x, bv); h.y = fmaf(w, xv.y, bv);
    h.z = fmaf(w, xv.z, bv); h.w = fmaf(w, xv.w, bv);
    ((float4*)g_h0)[i4] = h;
}

// build act image (ping 0) from g_h0
__global__ void __launch_bounds__(512, 1) img_build()
{
    const int blk = blockIdx.x;
    const int tid = threadIdx.x;
    const int b   = blk >> 6;
    const int t0  = (blk & 63) * TT;
    const int st_t = tid & 127;
    const int quar = tid >> 7;
    const float* src = g_h0 + (size_t)b * CC * TLEN + t0 + st_t;
    const uint32_t rowbase = (uint32_t)st_t * 256;
    const uint32_t rmask   = (uint32_t)(st_t & 7);
    char* ih = (char*)&g_img[0][blk][0][0];
    char* il = (char*)&g_img[0][blk][1][0];
#pragma unroll
    for (int jb = 0; jb < 4; ++jb) {
        int cc0 = quar * 32 + jb * 8;
        uint32_t hreg[4], lreg[4];
#pragma unroll
        for (int e = 0; e < 4; ++e) {
            float v0 = __ldg(src + (size_t)(cc0 + 2 * e) * TLEN);
            float v1 = __ldg(src + (size_t)(cc0 + 2 * e + 1) * TLEN);
            uint32_t h2 = cvt_bf16x2(v1, v0);
            hreg[e] = h2;
            lreg[e] = cvt_bf16x2(v1 - bfhi_f(h2), v0 - bflo_f(h2));
        }
        uint32_t off = rowbase + ((((uint32_t)(cc0 >> 3)) ^ rmask) << 4);
        *(uint4*)(ih + off) = make_uint4(hreg[0], hreg[1], hreg[2], hreg[3]);
        *(uint4*)(il + off) = make_uint4(lreg[0], lreg[1], lreg[2], lreg[3]);
    }
}

// ---------------- fused 3-term matrix pass ----------------
__device__ __forceinline__ void mma_mat3(float (&acc)[2][4][4],
                                         uint32_t wHi, uint32_t wLo,
                                         uint32_t xH, uint32_t xL,
                                         uint32_t aoff, uint32_t boff,
                                         uint32_t lmask, uint32_t asel, uint32_t bsel)
{
#pragma unroll
    for (int ks = 0; ks < 8; ++ks) {
        uint32_t acu = (((uint32_t)(2 * ks) + asel) << 4) ^ lmask;
        uint32_t ah0[4], ah1[4], al0[4], al1[4];
        LDSM4(ah0, wHi + aoff + acu);
        LDSM4(ah1, wHi + aoff + 4096 + acu);
        LDSM4(al0, wLo + aoff + acu);
        LDSM4(al1, wLo + aoff + 4096 + acu);
        uint32_t bcu = (((uint32_t)(2 * ks) + bsel) << 4) ^ lmask;
#pragma unroll
        for (int ntp = 0; ntp < 2; ++ntp) {
            uint32_t bh[4], bl[4];
            LDSM4(bh, xH + boff + (uint32_t)ntp * 4096 + bcu);
            LDSM4(bl, xL + boff + (uint32_t)ntp * 4096 + bcu);
            MMA_BF16(acc[0][2 * ntp],     ah0, bh[0], bh[1]);
            MMA_BF16(acc[0][2 * ntp + 1], ah0, bh[2], bh[3]);
            MMA_BF16(acc[1][2 * ntp],     ah1, bh[0], bh[1]);
            MMA_BF16(acc[1][2 * ntp + 1], ah1, bh[2], bh[3]);
            MMA_BF16(acc[0][2 * ntp],     ah0, bl[0], bl[1]);
            MMA_BF16(acc[0][2 * ntp + 1], ah0, bl[2], bl[3]);
            MMA_BF16(acc[1][2 * ntp],     ah1, bl[0], bl[1]);
            MMA_BF16(acc[1][2 * ntp + 1], ah1, bl[2], bl[3]);
            MMA_BF16(acc[0][2 * ntp],     al0, bh[0], bh[1]);
            MMA_BF16(acc[0][2 * ntp + 1], al0, bh[2], bh[3]);
            MMA_BF16(acc[1][2 * ntp],     al1, bh[0], bh[1]);
            MMA_BF16(acc[1][2 * ntp + 1], al1, bh[2], bh[3]);
        }
    }
}

// ---------------- fused layer kernel ----------------
__global__ void __launch_bounds__(512, 1)
layer_kernel(int layer, int dil, int ping,
             const float* __restrict__ b_dil, const float* __restrict__ b_tanh,
             const float* __restrict__ b_sig, const float* __restrict__ b_skip,
             float* __restrict__ out_base)
{
    extern __shared__ char smem[];
    const uint32_t sb = smem_u32(smem);
    const int tid = threadIdx.x;
    const int wid = tid >> 5, lane = tid & 31;
    const int wm = wid & 3, wn = wid >> 2;

    const int blk = blockIdx.x;
    const int b   = blk >> 6;
    const int t0  = (blk & 63) * TT;
    float* outputs = out_base + ((size_t)layer * BB + b) * CC * TLEN;
    float* skips   = out_base + (size_t)LL * BB * CC * TLEN + ((size_t)layer * BB + b) * CC * TLEN;

    const uint32_t B0 = sb + SMB(0), B1 = sb + SMB(1), B2 = sb + SMB(2),
                   B3 = sb + SMB(3), B4 = sb + SMB(4), B5 = sb + SMB(5),
                   B6 = sb + SMB(6);
    const uint32_t BIAS = sb + SM_BIAS;   // 4 sets x 512B: dil, tanh, sig, skip

    // single weight plane cp.async (16KB -> one 32KB-slot plane, no commit)
    auto prefetch_plane = [&](int m, int hl, uint32_t dst) {
        const char* g = (const char*)(g_wimg + ((size_t)(layer * 5 + m) * 2 + hl) * 16384);
#pragma unroll
        for (int j = 0; j < 4; ++j)
            CP_ASYNC16(dst + tid * 16 + j * 8192, g + tid * 16 + j * 8192);
    };

    // hdel plane copy: swizzle-remapped cp.async from previous-layer image (no commit)
    auto hdel_cp = [&](int pl, uint32_t dstbase) {
#pragma unroll
        for (int j = 0; j < 4; ++j) {
            int u = tid * 4 + j;
            int row = u >> 4, cu = u & 15;
            int sg = t0 + row - dil;
            const char* src;
            if (sg >= 0) {
                int stile = b * 64 + (sg >> 7);
                int srow  = sg & 127;
                int scu   = cu ^ ((row ^ srow) & 7);
                src = (const char*)&g_img[ping][stile][pl][0] + srow * 256 + scu * 16;
            } else {
                src = (const char*)g_zero;
            }
            CP_ASYNC16(dstbase + (uint32_t)u * 16, src);
        }
    };

    const int st_t = tid & 127;
    const int quar = tid >> 7;
    const uint32_t rowbase = (uint32_t)st_t * 256;
    const uint32_t rmask   = (uint32_t)(st_t & 7);

    const uint32_t lmask = (uint32_t)(lane & 7) << 4;
    const uint32_t asel = (uint32_t)((lane >> 4) & 1);
    const uint32_t bsel = (uint32_t)((lane >> 3) & 1);
    const uint32_t aoff = (uint32_t)(wm * 32 + (lane & 7) + ((lane >> 3) & 1) * 8) * 256;
    const uint32_t boff = (uint32_t)(wn * 32 + (lane & 7) + ((lane >> 4) & 1) * 8) * 256;
    uint32_t sunit[2];
#pragma unroll
    for (int mt = 0; mt < 2; ++mt)
        sunit[mt] = (((uint32_t)(wm * 4 + mt * 2 + ((lane >> 3) & 1))) << 4) ^ lmask;

    float acc[2][4][4];
    float flt[2][4][4];

    // bias base byte offset for this thread within a 512B set
    const uint32_t bias_t = (uint32_t)(wm * 32 + (lane >> 2)) * 4;

    auto init_acc = [&](int set) {
#pragma unroll
        for (int mt = 0; mt < 2; ++mt) {
            float v0, v1;
            asm volatile("ld.shared.f32 %0, [%1];" : "=f"(v0)
                         : "r"(BIAS + (uint32_t)set * 512 + bias_t + (uint32_t)mt * 64));
            asm volatile("ld.shared.f32 %0, [%1];" : "=f"(v1)
                         : "r"(BIAS + (uint32_t)set * 512 + bias_t + (uint32_t)mt * 64 + 32));
#pragma unroll
            for (int nt = 0; nt < 4; ++nt) {
                acc[mt][nt][0] = v0; acc[mt][nt][1] = v0;
                acc[mt][nt][2] = v1; acc[mt][nt][3] = v1;
            }
        }
    };

    // ======== C0: hcur image -> B4,B5 ; hdel-hi -> B6 ; biases -> smem ========
    {
        const char* gih = (const char*)&g_img[ping][blk][0][0];
        const char* gil = (const char*)&g_img[ping][blk][1][0];
#pragma unroll
        for (int j = 0; j < 4; ++j)
            CP_ASYNC16(B4 + tid * 16 + j * 8192, gih + tid * 16 + j * 8192);
#pragma unroll
        for (int j = 0; j < 4; ++j)
            CP_ASYNC16(B5 + tid * 16 + j * 8192, gil + tid * 16 + j * 8192);
        hdel_cp(0, B6);
        if (tid < 128) {
            const float* barr[4] = {b_dil, b_tanh, b_sig, b_skip};
            const char* src = (const char*)(barr[tid >> 5] + layer * CC) + (tid & 31) * 16;
            CP_ASYNC16(BIAS + (uint32_t)(tid >> 5) * 512 + (uint32_t)(tid & 31) * 16, src);
        }
        CP_COMMIT();
    }
    prefetch_plane(1, 0, B0); prefetch_plane(1, 1, B1); CP_COMMIT();   // C1: W1
    prefetch_plane(0, 0, B2); prefetch_plane(0, 1, B3); CP_COMMIT();   // C2: W0

    // ======== G1a: acc += W1 (x) hcur ========
    CP_WAIT(1);                // C0 + C1 done (C2 may fly)
    __syncthreads();           // S1
    init_acc(0);
    mma_mat3(acc, B0, B1, B4, B5, aoff, boff, lmask, asel, bsel);

    // ---- outputs copy: reconstruct fp32 h from hcur tiles
    {
        float* outp = outputs + t0 + st_t;
#pragma unroll
        for (int jb = 0; jb < 4; ++jb) {
            int cc0 = quar * 32 + jb * 8;
            uint32_t off = rowbase + ((((uint32_t)(cc0 >> 3)) ^ rmask) << 4);
            uint4 hv = *(const uint4*)(smem + SMB(4) + off);
            uint4 lv = *(const uint4*)(smem + SMB(5) + off);
            uint32_t he[4] = {hv.x, hv.y, hv.z, hv.w};
            uint32_t le[4] = {lv.x, lv.y, lv.z, lv.w};
#pragma unroll
            for (int e = 0; e < 4; ++e) {
                outp[(size_t)(cc0 + 2 * e) * TLEN]     = bflo_f(he[e]) + bflo_f(le[e]);
                outp[(size_t)(cc0 + 2 * e + 1) * TLEN] = bfhi_f(he[e]) + bfhi_f(le[e]);
            }
        }
    }
    __syncthreads();           // S2a: B0,B1,B4,B5 free

    // ======== G1b prep: hdel-lo, Wt, Ws-hi all in flight ========
    hdel_cp(1, B4); CP_COMMIT();                                        // C3: hdel-lo -> B4
    prefetch_plane(2, 0, B0); prefetch_plane(2, 1, B1); CP_COMMIT();    // C4: Wt -> B0,B1
    prefetch_plane(3, 0, B5); CP_COMMIT();                              // C5: Ws-hi -> B5
    CP_WAIT(2);                // C2 (W0) + C3 (hdel-lo) done; C4,C5 fly
    __syncthreads();           // S2b
    mma_mat3(acc, B2, B3, B6, B4, aoff, boff, lmask, asel, bsel);
    __syncthreads();           // S3a: B2,B3,B6,B4 free

    // ======== epi1: xdil -> (B2,B3); Ws-lo + Wk-hi in flight ========
    prefetch_plane(3, 1, B6); CP_COMMIT();                              // C6: Ws-lo -> B6
    prefetch_plane(4, 0, B4); CP_COMMIT();                              // C7: Wk-hi -> B4
#pragma unroll
    for (int mt = 0; mt < 2; ++mt)
#pragma unroll
        for (int ntp = 0; ntp < 2; ++ntp) {
            uint32_t rh[4], rl[4];
#pragma unroll
            for (int q = 0; q < 4; ++q) {
                float d0 = acc[mt][2 * ntp + (q >> 1)][(q & 1) * 2 + 0];
                float d1 = acc[mt][2 * ntp + (q >> 1)][(q & 1) * 2 + 1];
                uint32_t h = cvt_bf16x2(d1, d0);
                rh[q] = h;
                rl[q] = cvt_bf16x2(d1 - bfhi_f(h), d0 - bflo_f(h));
            }
            uint32_t ad = boff + (uint32_t)ntp * 4096 + sunit[mt];
            STSM4T(B2 + ad, rh);
            STSM4T(B3 + ad, rl);
        }
    CP_WAIT(1);                // C4 (Wt) + C5 (Ws-hi) + C6 (Ws-lo) done; C7 flies
    __syncthreads();           // S3b: xdil + Wt + Ws all visible

    // ======== G2 + G3 merged: filt then gate, NO intermediate barrier ========
    init_acc(1);
    mma_mat3(acc, B0, B1, B2, B3, aoff, boff, lmask, asel, bsel);
#pragma unroll
    for (int mt = 0; mt < 2; ++mt)
#pragma unroll
        for (int nt = 0; nt < 4; ++nt)
#pragma unroll
            for (int q = 0; q < 4; ++q)
                flt[mt][nt][q] = acc[mt][nt][q];
    init_acc(2);
    mma_mat3(acc, B5, B6, B2, B3, aoff, boff, lmask, asel, bsel);
    __syncthreads();           // S4a: B0,B1 (Wt) + B5,B6 (Ws) free

    // ======== epi3: gated; h_next image -> (B5,B6); xh -> (B2,B3) ========
    prefetch_plane(4, 1, B0); CP_COMMIT();                              // C8: Wk-lo -> B0
#pragma unroll
    for (int mt = 0; mt < 2; ++mt)
#pragma unroll
        for (int ntp = 0; ntp < 2; ++ntp) {
            uint32_t ad = boff + (uint32_t)ntp * 4096 + sunit[mt];
            uint32_t xdh[4], xdl[4];
            LDSM4T(xdh, B2 + ad);
            LDSM4T(xdl, B3 + ad);
            uint32_t hnh[4], hnl[4], sh[4], sl[4];
#pragma unroll
            for (int q = 0; q < 4; ++q) {
                int nt = 2 * ntp + (q >> 1), hh = q & 1;
                float xd0 = bflo_f(xdh[q]) + bflo_f(xdl[q]);
                float xd1 = bfhi_f(xdh[q]) + bfhi_f(xdl[q]);
                float xh0 = gated(flt[mt][nt][hh * 2 + 0], acc[mt][nt][hh * 2 + 0]);
                float xh1 = gated(flt[mt][nt][hh * 2 + 1], acc[mt][nt][hh * 2 + 1]);
                float hn0 = xh0 + xd0, hn1 = xh1 + xd1;
                uint32_t h2 = cvt_bf16x2(hn1, hn0);
                hnh[q] = h2;
                hnl[q] = cvt_bf16x2(hn1 - bfhi_f(h2), hn0 - bflo_f(h2));
                uint32_t x2 = cvt_bf16x2(xh1, xh0);
                sh[q] = x2;
                sl[q] = cvt_bf16x2(xh1 - bfhi_f(x2), xh0 - bflo_f(x2));
            }
            STSM4T(B5 + ad, hnh);
            STSM4T(B6 + ad, hnl);
            STSM4T(B2 + ad, sh);   // xh overwrites xdil (per-warp disjoint regions)
            STSM4T(B3 + ad, sl);
        }
    init_acc(3);
    CP_WAIT(0);                // C7 (Wk-hi) + C8 (Wk-lo) done
    __syncthreads();           // S4b: xh + h_next visible, Wk loaded

    // ======== h_next image -> global ========
    {
        char* oih = (char*)&g_img[1 - ping][blk][0][0];
        char* oil = (char*)&g_img[1 - ping][blk][1][0];
#pragma unroll
        for (int j = 0; j < 4; ++j)
            *(uint4*)(oih + tid * 16 + j * 8192) = *(const uint4*)(smem + SMB(5) + tid * 16 + j * 8192);
#pragma unroll
        for (int j = 0; j < 4; ++j)
            *(uint4*)(oil + tid * 16 + j * 8192) = *(const uint4*)(smem + SMB(6) + tid * 16 + j * 8192);
    }

    // ======== G4: skip = Wk (x) xh  (Wk-hi in B4, Wk-lo in B0) ========
    mma_mat3(acc, B4, B0, B2, B3, aoff, boff, lmask, asel, bsel);
#pragma unroll
    for (int mt = 0; mt < 2; ++mt)
#pragma unroll
        for (int nt = 0; nt < 4; ++nt)
#pragma unroll
            for (int hh = 0; hh < 2; ++hh) {
                int o  = wm * 32 + mt * 16 + hh * 8 + (lane >> 2);
                int tg = t0 + wn * 32 + nt * 8 + (lane & 3) * 2;
                *(float2*)(skips + (size_t)o * TLEN + tg) =
                    make_float2(acc[mt][nt][hh * 2 + 0], acc[mt][nt][hh * 2 + 1]);
            }
}

// ---------------- host ----------------
extern "C" void kernel_launch(void* const* d_in, const int* in_sizes, int n_in,
                              void* d_out, int out_size)
{
    const float* x      = (const float*)d_in[0];
    const float* w_in   = (const float*)d_in[1];
    const float* b_in   = (const float*)d_in[2];
    const float* w_dil  = (const float*)d_in[3];
    const float* b_dil  = (const float*)d_in[4];
    const float* w_tanh = (const float*)d_in[5];
    const float* b_tanh = (const float*)d_in[6];
    const float* w_sig  = (const float*)d_in[7];
    const float* b_sig  = (const float*)d_in[8];
    const float* w_skip = (const float*)d_in[9];
    const float* b_skip = (const float*)d_in[10];
    float* out = (float*)d_out;

    cudaFuncSetAttribute(layer_kernel,
                         cudaFuncAttributeMaxDynamicSharedMemorySize, SMEM_TOTAL);

    prep_weights<<<(LL * 5 * CC * CC + 255) / 256, 256>>>(w_dil, w_tanh, w_sig, w_skip);
    input_conv<<<(BB * CC * TLEN / 4 + 255) / 256, 256>>>(x, w_in, b_in);
    img_build<<<NTILE, 512>>>();

    const int dils[LL] = {1, 2, 4, 8, 16, 32, 64, 128, 256, 512,
                          1, 2, 4, 8, 16, 32, 64, 128, 256, 512};
    for (int i = 0; i < LL; ++i) {
        layer_kernel<<<(BB * TLEN) / TT, 512, SMEM_TOTAL>>>(
            i, dils[i], i & 1, b_dil, b_tanh, b_sig, b_skip, out);
    }
}